// round 12
// baseline (speedup 1.0000x reference)
#include <cuda_runtime.h>
#include <cuda_bf16.h>
#include <cstdint>

#define DIMX      2048
#define D_STATE_  128
#define NHEADS_   64
#define HEADDIM_  64
#define D_INNER_  4096
#define D_IN_PROJ_ 8512
#define CONV_DIM_ 4352
#define BATCH_    2
#define SEQ_      2048
#define MROWS_    4096
#define DT_OFF_   8448
#define NPAD_IN_  8704
#define NCHUNK_   16
#define LCH_      128
#define PREP_CTAS 148

typedef __nv_bfloat16 bf16;
typedef unsigned long long u64;

// ---------------- device scratch ----------------
__device__ __align__(16)  float g_wpartA[PREP_CTAS];
__device__ __align__(16)  float g_wpartB[PREP_CTAS];
__device__ unsigned long long g_prep_ctr;
__device__ __align__(128) bf16  g_WqIn[(size_t)NPAD_IN_ * DIMX];
__device__ __align__(128) bf16  g_WqOut[(size_t)DIMX * D_INNER_];
__device__ __align__(128) bf16  g_Aq[(size_t)MROWS_ * DIMX];
__device__ __align__(128) bf16  g_Yq[(size_t)MROWS_ * D_INNER_];
__device__                float g_sA[MROWS_];
__device__                float g_sY[MROWS_];
__device__ __align__(128) float g_ZX[(size_t)MROWS_ * D_IN_PROJ_];
__device__ __align__(128) float g_Y[(size_t)MROWS_ * D_INNER_];
__device__ __align__(128) float g_alpha[(size_t)BATCH_ * NHEADS_ * SEQ_];
__device__ __align__(128) float g_Cc[(size_t)BATCH_ * SEQ_ * D_STATE_];
__device__ __align__(128) float g_S[(size_t)BATCH_ * NHEADS_ * NCHUNK_ * 8192];
__device__ __align__(128) float g_H[(size_t)BATCH_ * NHEADS_ * NCHUNK_ * 8192];

// ---------------- helpers ----------------
__device__ __forceinline__ uint32_t smem_u32(const void* p) {
    uint32_t a;
    asm("{ .reg .u64 t; cvta.to.shared.u64 t, %1; cvt.u32.u64 %0, t; }" : "=r"(a) : "l"(p));
    return a;
}
__device__ __forceinline__ u64 pk2(float lo, float hi) { u64 r; asm("mov.b64 %0, {%1,%2};" : "=l"(r) : "f"(lo), "f"(hi)); return r; }
__device__ __forceinline__ void upk2(float& lo, float& hi, u64 v) { asm("mov.b64 {%0,%1}, %2;" : "=f"(lo), "=f"(hi) : "l"(v)); }
__device__ __forceinline__ u64 fma2(u64 a, u64 b, u64 c) { u64 d; asm("fma.rn.f32x2 %0, %1, %2, %3;" : "=l"(d) : "l"(a), "l"(b), "l"(c)); return d; }
__device__ __forceinline__ u64 mul2(u64 a, u64 b) { u64 d; asm("mul.rn.f32x2 %0, %1, %2;" : "=l"(d) : "l"(a), "l"(b)); return d; }

// ---------------- block reduce ----------------
template<bool MAXOP>
__device__ __forceinline__ float blockReduce(float v) {
    __shared__ float sm[8];
    int lane = threadIdx.x & 31, wid = threadIdx.x >> 5;
    #pragma unroll
    for (int o = 16; o; o >>= 1) {
        float u = __shfl_xor_sync(0xffffffffu, v, o);
        v = MAXOP ? fmaxf(v, u) : v + u;
    }
    if (lane == 0) sm[wid] = v;
    __syncthreads();
    if (threadIdx.x < 32) {
        v = (lane < 8) ? sm[lane] : (MAXOP ? -3.4e38f : 0.f);
        #pragma unroll
        for (int o = 4; o; o >>= 1) {
            float u = __shfl_xor_sync(0xffffffffu, v, o);
            v = MAXOP ? fmaxf(v, u) : v + u;
        }
        if (lane == 0) sm[0] = v;
    }
    __syncthreads();
    v = sm[0];
    __syncthreads();
    return v;
}

// ---------------- persistent prep ----------------
#define NQ1 ((long)D_IN_PROJ_ * DIMX / 4)
#define NQ2 ((long)DIMX * D_INNER_ / 4)
#define NQP ((long)(NPAD_IN_ - D_IN_PROJ_) * DIMX / 4)
__global__ void __launch_bounds__(256) k_prep(const float* __restrict__ w1,
                                              const float* __restrict__ w2) {
    const int cta = blockIdx.x, tid = threadIdx.x;
    float s1 = 0.f, s2 = 0.f;
    for (long i = (long)cta * 256 + tid; i < NQ1; i += (long)PREP_CTAS * 256) {
        float4 v = ((const float4*)w1)[i];
        s1 += fabsf(v.x) + fabsf(v.y) + fabsf(v.z) + fabsf(v.w);
    }
    for (long i = (long)cta * 256 + tid; i < NQ2; i += (long)PREP_CTAS * 256) {
        float4 v = ((const float4*)w2)[i];
        s2 += fabsf(v.x) + fabsf(v.y) + fabsf(v.z) + fabsf(v.w);
    }
    s1 = blockReduce<false>(s1);
    s2 = blockReduce<false>(s2);
    if (tid == 0) { g_wpartA[cta] = s1; g_wpartB[cta] = s2; }

    __threadfence();
    __syncthreads();
    if (tid == 0) {
        unsigned long long old = atomicAdd(&g_prep_ctr, 1ull);
        unsigned long long target = (old / PREP_CTAS + 1ull) * PREP_CTAS;
        while (*((volatile unsigned long long*)&g_prep_ctr) < target) { }
    }
    __syncthreads();
    __threadfence();

    float a = 0.f, b = 0.f;
    for (int i = 0; i < PREP_CTAS; i++) { a += g_wpartA[i]; b += g_wpartB[i]; }
    const float sc0 = fmaxf(a / ((float)D_IN_PROJ_ * (float)DIMX), 1e-5f);
    const float sc1 = fmaxf(b / ((float)DIMX * (float)D_INNER_), 1e-5f);

    for (long q = (long)cta * 256 + tid; q < NQ1 + NQ2 + NQP; q += (long)PREP_CTAS * 256) {
        const float* w; bf16* dst; float sc; long i;
        if (q < NQ1) { w = w1; dst = g_WqIn;  sc = sc0; i = q * 4; }
        else if (q < NQ1 + NQ2) { w = w2; dst = g_WqOut; sc = sc1; i = (q - NQ1) * 4; }
        else {
            long i2 = (q - NQ1 - NQ2) * 4;
            *(uint2*)(g_WqIn + (size_t)D_IN_PROJ_ * DIMX + i2) = make_uint2(0, 0);
            continue;
        }
        float4 v = *(const float4*)(w + i);
        float vv[4] = {v.x, v.y, v.z, v.w};
        bf16 o[4];
        #pragma unroll
        for (int j = 0; j < 4; j++) {
            float ws = vv[j] / sc;
            float qq = (ws >= 0.f) ? floorf(ws + 0.5f) : ceilf(ws - 0.5f);
            o[j] = __float2bfloat16(fminf(fmaxf(qq, -1.f), 1.f));
        }
        *(uint2*)(dst + i) = *(uint2*)o;
    }
}

// ---------------- fused norms + activation quant ----------------
template<int W, int WHICH>
__global__ void k_actquant(const float* __restrict__ X, const float* __restrict__ nw) {
    constexpr int VPT = W / 1024;
    const int row = blockIdx.x, tid = threadIdx.x;
    const float4* xr = (const float4*)((WHICH ? g_Y : X) + (size_t)row * W);
    const float4* nw4 = (const float4*)nw;
    float4 x[VPT];
    float ss = 0.f;
    #pragma unroll
    for (int i = 0; i < VPT; i++) {
        x[i] = xr[tid + i * 256];
        ss += x[i].x * x[i].x + x[i].y * x[i].y + x[i].z * x[i].z + x[i].w * x[i].w;
    }
    ss = blockReduce<false>(ss);
    float r = rsqrtf(ss / (float)W + 1e-6f);
    float4 h[VPT]; float sum = 0.f, sq = 0.f;
    #pragma unroll
    for (int i = 0; i < VPT; i++) {
        float4 w4 = nw4[tid + i * 256];
        h[i].x = w4.x * x[i].x * r; h[i].y = w4.y * x[i].y * r;
        h[i].z = w4.z * x[i].z * r; h[i].w = w4.w * x[i].w * r;
        sum += h[i].x + h[i].y + h[i].z + h[i].w;
        sq  += h[i].x * h[i].x + h[i].y * h[i].y + h[i].z * h[i].z + h[i].w * h[i].w;
    }
    sum = blockReduce<false>(sum);
    sq  = blockReduce<false>(sq);
    float mean = sum / (float)W;
    float var  = sq / (float)W - mean * mean;
    float rv = rsqrtf(var + 1e-5f);
    float amax = 0.f;
    #pragma unroll
    for (int i = 0; i < VPT; i++) {
        h[i].x = (h[i].x - mean) * rv; h[i].y = (h[i].y - mean) * rv;
        h[i].z = (h[i].z - mean) * rv; h[i].w = (h[i].w - mean) * rv;
        amax = fmaxf(amax, fmaxf(fmaxf(fabsf(h[i].x), fabsf(h[i].y)),
                                 fmaxf(fabsf(h[i].z), fabsf(h[i].w))));
    }
    amax = blockReduce<true>(amax);
    float scale = 127.f / fmaxf(amax, 1e-5f);
    bf16* Q = WHICH ? g_Yq : g_Aq;
    #pragma unroll
    for (int i = 0; i < VPT; i++) {
        bf16 o[4];
        float c[4] = {h[i].x, h[i].y, h[i].z, h[i].w};
        #pragma unroll
        for (int j = 0; j < 4; j++) {
            float q = rintf(c[j] * scale);
            o[j] = __float2bfloat16(fminf(fmaxf(q, -128.f), 127.f));
        }
        *(uint2*)(Q + (size_t)row * W + (tid + i * 256) * 4) = *(uint2*)o;
    }
    if (tid == 0) (WHICH ? g_sY : g_sA)[row] = scale;
}

// ---------------- pipelined bf16 mma.sync GEMM (measured, unchanged) ------
#define BMg 128
#define BNg 128
#define BKg 32
#define LDSg 40
#define STG_ELEMS (BMg * LDSg)
#define STG_BYTES (2 * STG_ELEMS * 2)
#define GEMM_SMEM (4 * STG_BYTES)

template<int MODE>
__global__ void __launch_bounds__(256, 2) k_gemm(const float* __restrict__ resid,
                                                 float* __restrict__ outp) {
    constexpr int K = MODE ? D_INNER_ : DIMX;
    constexpr int N = MODE ? DIMX : D_IN_PROJ_;
    constexpr int NS = K / BKg;

    const bf16*  __restrict__ A  = MODE ? g_Yq : g_Aq;
    const bf16*  __restrict__ Bw = MODE ? g_WqOut : g_WqIn;
    const float* __restrict__ rs = MODE ? g_sY : g_sA;
    float*       __restrict__ C  = MODE ? outp : g_ZX;

    extern __shared__ char smem[];
    const uint32_t sb = smem_u32(smem);

    const int tid = threadIdx.x;
    const int lane = tid & 31, wid = tid >> 5;
    const int wm = wid & 1, wn = wid >> 1;
    const int m0 = blockIdx.y * BMg, n0 = blockIdx.x * BNg;
    const int mw = wm * 64, nwp = wn * 32;

    float acc[4][4][4];
    #pragma unroll
    for (int a = 0; a < 4; a++)
        #pragma unroll
        for (int b = 0; b < 4; b++)
            #pragma unroll
            for (int c = 0; c < 4; c++) acc[a][b][c] = 0.f;

    const bf16* gsrc[4];
    uint32_t sdst[4];
    #pragma unroll
    for (int i = 0; i < 4; i++) {
        int q = tid + i * 256;
        if (q < 512) {
            int row = q >> 2, c = q & 3;
            gsrc[i] = A + (size_t)(m0 + row) * K + c * 8;
            sdst[i] = (uint32_t)(row * LDSg + c * 8) * 2;
        } else {
            int qq = q - 512, row = qq >> 2, c = qq & 3;
            gsrc[i] = Bw + (size_t)(n0 + row) * K + c * 8;
            sdst[i] = (uint32_t)(STG_ELEMS + row * LDSg + c * 8) * 2;
        }
    }

    #define LOAD_STAGE(s_) do { \
        uint32_t base_ = sb + ((s_) & 3) * STG_BYTES; \
        _Pragma("unroll") \
        for (int i_ = 0; i_ < 4; i_++) \
            asm volatile("cp.async.cg.shared.global [%0], [%1], 16;" \
                :: "r"(base_ + sdst[i_]), "l"(gsrc[i_] + (s_) * BKg) : "memory"); \
        asm volatile("cp.async.commit_group;" ::: "memory"); \
    } while (0)

    uint32_t aOff[4], bOff[2];
    {
        int rA = mw + (lane & 15);
        int cA = (lane >> 4) * 8;
        #pragma unroll
        for (int fm = 0; fm < 4; fm++)
            aOff[fm] = (uint32_t)((rA + fm * 16) * LDSg + cA) * 2;
        int rB = nwp + ((lane >> 4) << 3) + (lane & 7);
        int cB = ((lane >> 3) & 1) * 8;
        #pragma unroll
        for (int fb = 0; fb < 2; fb++)
            bOff[fb] = (uint32_t)(STG_ELEMS + (rB + fb * 16) * LDSg + cB) * 2;
    }

    LOAD_STAGE(0); LOAD_STAGE(1); LOAD_STAGE(2);

    for (int s = 0; s < NS; s++) {
        asm volatile("cp.async.wait_group 2;" ::: "memory");
        __syncthreads();
        if (s + 3 < NS) LOAD_STAGE(s + 3);

        const uint32_t base = sb + (s & 3) * STG_BYTES;
        #pragma unroll
        for (int ks = 0; ks < BKg; ks += 16) {
            unsigned af[4][4], bfr[4][2];
            #pragma unroll
            for (int fm = 0; fm < 4; fm++)
                asm volatile("ldmatrix.sync.aligned.m8n8.x4.shared.b16 {%0,%1,%2,%3}, [%4];"
                    : "=r"(af[fm][0]), "=r"(af[fm][1]), "=r"(af[fm][2]), "=r"(af[fm][3])
                    : "r"(base + aOff[fm] + (uint32_t)(ks * 2)));
            #pragma unroll
            for (int fb = 0; fb < 2; fb++) {
                unsigned q0, q1, q2, q3;
                asm volatile("ldmatrix.sync.aligned.m8n8.x4.shared.b16 {%0,%1,%2,%3}, [%4];"
                    : "=r"(q0), "=r"(q1), "=r"(q2), "=r"(q3)
                    : "r"(base + bOff[fb] + (uint32_t)(ks * 2)));
                bfr[fb * 2][0] = q0; bfr[fb * 2][1] = q1;
                bfr[fb * 2 + 1][0] = q2; bfr[fb * 2 + 1][1] = q3;
            }
            #pragma unroll
            for (int fm = 0; fm < 4; fm++)
                #pragma unroll
                for (int fn = 0; fn < 4; fn++)
                    asm volatile("mma.sync.aligned.m16n8k16.row.col.f32.bf16.bf16.f32 "
                        "{%0,%1,%2,%3},{%4,%5,%6,%7},{%8,%9},{%0,%1,%2,%3};"
                        : "+f"(acc[fm][fn][0]), "+f"(acc[fm][fn][1]),
                          "+f"(acc[fm][fn][2]), "+f"(acc[fm][fn][3])
                        : "r"(af[fm][0]), "r"(af[fm][1]), "r"(af[fm][2]), "r"(af[fm][3]),
                          "r"(bfr[fn][0]), "r"(bfr[fn][1]));
        }
    }

    const int mr = m0 + mw + (lane >> 2);
    const int nc = n0 + nwp + (lane & 3) * 2;
    #pragma unroll
    for (int fm = 0; fm < 4; fm++) {
        int m = mr + fm * 16;
        float inv0 = 1.f / rs[m];
        float inv1 = 1.f / rs[m + 8];
        #pragma unroll
        for (int fn = 0; fn < 4; fn++) {
            int n = nc + fn * 8;
            if (n < N) {
                size_t o0 = (size_t)m * N + n;
                size_t o8 = (size_t)(m + 8) * N + n;
                float v0 = acc[fm][fn][0] * inv0;
                float v1 = acc[fm][fn][1] * inv0;
                float v2 = acc[fm][fn][2] * inv1;
                float v3 = acc[fm][fn][3] * inv1;
                if (MODE) {
                    v0 += resid[o0]; v1 += resid[o0 + 1];
                    v2 += resid[o8]; v3 += resid[o8 + 1];
                }
                C[o0] = v0; C[o0 + 1] = v1; C[o8] = v2; C[o8 + 1] = v3;
            }
        }
    }
    #undef LOAD_STAGE
}

// ---------------- PASS 1: local scan, 256 thr, 32 states/thread -----------
// conv-space layout within CONV_DIM_: x [0,4096), B [4096,4224), C [4224,4352)
__global__ void __launch_bounds__(256) k_scan1(const float* __restrict__ A_log,
                                               const float* __restrict__ Dv,
                                               const float* __restrict__ dt_bias,
                                               const float* __restrict__ cw,
                                               const float* __restrict__ cb) {
    const int chunk = blockIdx.x, bh = blockIdx.y;
    const int h = bh & (NHEADS_ - 1);
    const int b = bh >> 6;
    const int l0 = chunk * LCH_;
    const int t = threadIdx.x;
    const int pc = t & 63, gc = t >> 6, n0 = gc * 32;

    __shared__ __align__(16) float xs[2][4][64];
    __shared__ __align__(16) float Bsh[2][4][128], Csh[2][4][128];
    __shared__ __align__(16) float ypart[2][4][4][64];
    __shared__ float sdt[2][4], sdA[2][4];

    const float Ah   = -expf(A_log[h]);
    const float Dh   = Dv[h];
    const float bias = dt_bias[h];

    u64 h2[16];
    #pragma unroll
    for (int i = 0; i < 16; i++) h2[i] = 0ull;

    const float* zxbase = g_ZX + (size_t)(b * SEQ_) * D_IN_PROJ_;

    // channel 0 (conv-space index): t<64 -> x[h*64+t]; t<192 -> B[t-64]; else C[t-192]
    const int cc0 = (t < 64) ? (h * 64 + t)
                  : ((t < 192) ? (4096 + (t - 64)) : (4224 + (t - 192)));
    const float* g0 = zxbase + D_INNER_ + cc0;
    const float w00 = cw[cc0 * 4], w01 = cw[cc0 * 4 + 1],
                w02 = cw[cc0 * 4 + 2], w03 = cw[cc0 * 4 + 3];
    const float cb0 = cb[cc0];
    float a03 = 0.f, a02 = 0.f, a01 = 0.f;
    if (chunk > 0) {
        a03 = g0[(size_t)(l0 - 3) * D_IN_PROJ_];
        a02 = g0[(size_t)(l0 - 2) * D_IN_PROJ_];
        a01 = g0[(size_t)(l0 - 1) * D_IN_PROJ_];
    }

    // channel 1: t<64 -> C[64+t] (conv, conv-space 4224+64+t); t==64 -> dt (raw)
    const bool hasC1 = (t < 64);
    const bool isDT  = (t == 64);
    const float* g1 = nullptr;
    float w10 = 0.f, w11 = 0.f, w12 = 0.f, w13 = 0.f, cb1 = 0.f;
    float a13 = 0.f, a12 = 0.f, a11 = 0.f;
    if (hasC1) {
        const int cc1 = 4224 + 64 + t;
        g1 = zxbase + D_INNER_ + cc1;
        w10 = cw[cc1 * 4]; w11 = cw[cc1 * 4 + 1];
        w12 = cw[cc1 * 4 + 2]; w13 = cw[cc1 * 4 + 3];
        cb1 = cb[cc1];
        if (chunk > 0) {
            a13 = g1[(size_t)(l0 - 3) * D_IN_PROJ_];
            a12 = g1[(size_t)(l0 - 2) * D_IN_PROJ_];
            a11 = g1[(size_t)(l0 - 1) * D_IN_PROJ_];
        }
    } else if (isDT) {
        g1 = zxbase + DT_OFF_ + h;
    }

    float r0[4], r1[4] = {0.f, 0.f, 0.f, 0.f};
    #pragma unroll
    for (int s = 0; s < 4; s++) r0[s] = g0[(size_t)(l0 + s) * D_IN_PROJ_];
    if (g1) {
        #pragma unroll
        for (int s = 0; s < 4; s++) r1[s] = g1[(size_t)(l0 + s) * D_IN_PROJ_];
    }

    float* yrow = g_Y + (size_t)(b * SEQ_ + l0) * D_INNER_ + h * 64;
    float* arow = g_alpha + (size_t)bh * SEQ_ + l0;
    float* ccw = g_Cc + (size_t)(b * SEQ_ + l0) * D_STATE_;
    float aprod = 1.f;

    for (int blk = 0; blk < LCH_ / 4; blk++) {
        const int p = blk & 1, q = p ^ 1;
        float v0[4], v1[4];
        {   // conv ch0
            float w3r = a03, w2r = a02, w1r = a01;
            #pragma unroll
            for (int s = 0; s < 4; s++) {
                float a = fmaf(w03, r0[s], fmaf(w02, w1r, fmaf(w01, w2r, fmaf(w00, w3r, cb0))));
                v0[s] = a / (1.f + expf(-a));
                w3r = w2r; w2r = w1r; w1r = r0[s];
            }
            a03 = r0[1]; a02 = r0[2]; a01 = r0[3];
        }
        if (hasC1) {
            float w3r = a13, w2r = a12, w1r = a11;
            #pragma unroll
            for (int s = 0; s < 4; s++) {
                float a = fmaf(w13, r1[s], fmaf(w12, w1r, fmaf(w11, w2r, fmaf(w10, w3r, cb1))));
                v1[s] = a / (1.f + expf(-a));
                w3r = w2r; w2r = w1r; w1r = r1[s];
            }
            a13 = r1[1]; a12 = r1[2]; a11 = r1[3];
        } else {
            #pragma unroll
            for (int s = 0; s < 4; s++) v1[s] = r1[s];
        }

        if (t < 64) {
            #pragma unroll
            for (int s = 0; s < 4; s++) {
                xs[p][s][t] = v0[s];
                Csh[p][s][64 + t] = v1[s];
            }
        } else if (t < 192) {
            #pragma unroll
            for (int s = 0; s < 4; s++) Bsh[p][s][t - 64] = v0[s];
        } else {
            #pragma unroll
            for (int s = 0; s < 4; s++) Csh[p][s][t - 192] = v0[s];
        }
        if (isDT) {
            #pragma unroll
            for (int s = 0; s < 4; s++) {
                float d = v1[s] + bias;
                float sp = fmaxf(d, 0.f) + log1pf(expf(-fabsf(d)));
                float dA = expf(sp * Ah);
                sdt[p][s] = sp; sdA[p][s] = dA;
                aprod *= dA; arow[4 * blk + s] = aprod;
            }
        }
        if (h == 0) {
            if (t >= 192) {
                #pragma unroll
                for (int s = 0; s < 4; s++)
                    ccw[(size_t)(4 * blk + s) * D_STATE_ + (t - 192)] = v0[s];
            } else if (t < 64) {
                #pragma unroll
                for (int s = 0; s < 4; s++)
                    ccw[(size_t)(4 * blk + s) * D_STATE_ + 64 + t] = v1[s];
            }
        }
        __syncthreads();

        if (blk > 0 && t < 64) {
            #pragma unroll
            for (int s = 0; s < 4; s++) {
                float ysum = ypart[q][s][0][t] + ypart[q][s][1][t]
                           + ypart[q][s][2][t] + ypart[q][s][3][t];
                yrow[(size_t)(4 * (blk - 1) + s) * D_INNER_ + t] = ysum + Dh * xs[q][s][t];
            }
        }

        float r0n[4] = {0.f, 0.f, 0.f, 0.f}, r1n[4] = {0.f, 0.f, 0.f, 0.f};
        if (blk + 1 < LCH_ / 4) {
            #pragma unroll
            for (int s = 0; s < 4; s++)
                r0n[s] = g0[(size_t)(l0 + 4 * blk + 4 + s) * D_IN_PROJ_];
            if (g1) {
                #pragma unroll
                for (int s = 0; s < 4; s++)
                    r1n[s] = g1[(size_t)(l0 + 4 * blk + 4 + s) * D_IN_PROJ_];
            }
        }

        #pragma unroll
        for (int s = 0; s < 4; s++) {
            const float dA = sdA[p][s];
            const float cf = sdt[p][s] * xs[p][s][pc];
            const u64 dA2 = pk2(dA, dA);
            const u64 cf2 = pk2(cf, cf);
            const ulonglong2* Bv = (const ulonglong2*)&Bsh[p][s][n0];
            const ulonglong2* Cv = (const ulonglong2*)&Csh[p][s][n0];
            u64 y2a = 0ull, y2b = 0ull;
            #pragma unroll
            for (int i = 0; i < 8; i++) {
                ulonglong2 B2 = Bv[i];
                ulonglong2 C2 = Cv[i];
                h2[2 * i]     = fma2(h2[2 * i],     dA2, mul2(cf2, B2.x));
                y2a = fma2(h2[2 * i],     C2.x, y2a);
                h2[2 * i + 1] = fma2(h2[2 * i + 1], dA2, mul2(cf2, B2.y));
                y2b = fma2(h2[2 * i + 1], C2.y, y2b);
            }
            float la, ha, lb, hb;
            upk2(la, ha, y2a); upk2(lb, hb, y2b);
            ypart[p][s][gc][pc] = (la + ha) + (lb + hb);
        }

        #pragma unroll
        for (int s = 0; s < 4; s++) { r0[s] = r0n[s]; r1[s] = r1n[s]; }
    }
    __syncthreads();
    if (t < 64) {
        const int q = (LCH_ / 4 - 1) & 1;
        #pragma unroll
        for (int s = 0; s < 4; s++) {
            float ysum = ypart[q][s][0][t] + ypart[q][s][1][t]
                       + ypart[q][s][2][t] + ypart[q][s][3][t];
            yrow[(size_t)(LCH_ - 4 + s) * D_INNER_ + t] = ysum + Dh * xs[q][s][t];
        }
    }
    float* srow = g_S + ((size_t)bh * NCHUNK_ + chunk) * 8192 + (size_t)pc * 128 + n0;
    float4* s4 = (float4*)srow;
    #pragma unroll
    for (int i = 0; i < 8; i++) {
        float4 v;
        upk2(v.x, v.y, h2[2 * i]);
        upk2(v.z, v.w, h2[2 * i + 1]);
        s4[i] = v;
    }
}

// ---------------- PASS 2: chunk-state prefix ----------------
__global__ void __launch_bounds__(512) k_scan2() {
    const int bh = blockIdx.x, t = threadIdx.x;
    float4 H[4];
    #pragma unroll
    for (int i = 0; i < 4; i++) H[i] = make_float4(0.f, 0.f, 0.f, 0.f);
    for (int c = 0; c < NCHUNK_; c++) {
        if (c > 0) {
            float4* hw = (float4*)(g_H + ((size_t)bh * NCHUNK_ + c) * 8192) + t * 4;
            #pragma unroll
            for (int i = 0; i < 4; i++) hw[i] = H[i];
        }
        float P = g_alpha[(size_t)bh * SEQ_ + c * LCH_ + LCH_ - 1];
        const float4* sv = (const float4*)(g_S + ((size_t)bh * NCHUNK_ + c) * 8192) + t * 4;
        #pragma unroll
        for (int i = 0; i < 4; i++) {
            float4 s = sv[i];
            H[i].x = fmaf(P, H[i].x, s.x);
            H[i].y = fmaf(P, H[i].y, s.y);
            H[i].z = fmaf(P, H[i].z, s.z);
            H[i].w = fmaf(P, H[i].w, s.w);
        }
    }
}

// ---------------- PASS 3: correction + gating (256 thr, 32n/thread) -------
__global__ void __launch_bounds__(256, 2) k_scan3() {
    extern __shared__ float Cs[];                 // [128][128]
    __shared__ __align__(16) float ypart3[8][4][64];
    __shared__ float alf[LCH_];

    const int chunk = blockIdx.x, bh = blockIdx.y;
    const int h = bh & (NHEADS_ - 1);
    const int b = bh >> 6;
    const int l0 = chunk * LCH_;
    const int t = threadIdx.x;
    const int pc = t & 63, gc = t >> 6, n0 = gc * 32;

    {
        const float4* csrc = (const float4*)(g_Cc + (size_t)(b * SEQ_ + l0) * D_STATE_);
        float4* cdst = (float4*)Cs;
        #pragma unroll
        for (int k = 0; k < 16; k++) cdst[t + k * 256] = csrc[t + k * 256];
    }
    if (t < LCH_) alf[t] = g_alpha[(size_t)bh * SEQ_ + l0 + t];

    u64 H2[16];
    if (chunk > 0) {
        const float4* hv = (const float4*)(g_H + ((size_t)bh * NCHUNK_ + chunk) * 8192
                                           + (size_t)pc * 128 + n0);
        #pragma unroll
        for (int i = 0; i < 8; i++) {
            float4 v = hv[i];
            H2[2 * i]     = pk2(v.x, v.y);
            H2[2 * i + 1] = pk2(v.z, v.w);
        }
    } else {
        #pragma unroll
        for (int i = 0; i < 16; i++) H2[i] = 0ull;
    }
    __syncthreads();

    float* yrow = g_Y + (size_t)(b * SEQ_ + l0) * D_INNER_ + h * 64;
    const float* zrow = g_ZX + (size_t)(b * SEQ_ + l0) * D_IN_PROJ_ + h * 64;

    for (int lb = 0; lb < 16; lb++) {
        #pragma unroll
        for (int j = 0; j < 8; j++) {
            int l = lb * 8 + j;
            const ulonglong2* C2 = (const ulonglong2*)&Cs[l * 128 + n0];
            u64 y2a = 0ull, y2b = 0ull;
            #pragma unroll
            for (int i = 0; i < 8; i++) {
                ulonglong2 c2 = C2[i];
                y2a = fma2(H2[2 * i], c2.x, y2a);
                y2b = fma2(H2[2 * i + 1], c2.y, y2b);
            }
            float la, ha, lb2, hb;
            upk2(la, ha, y2a); upk2(lb2, hb, y2b);
            ypart3[j][gc][pc] = (la + ha) + (lb2 + hb);
        }
        __syncthreads();
        if (t < 64) {
            #pragma unroll
            for (int j = 0; j < 8; j++) {
                int l = lb * 8 + j;
                float corr = ypart3[j][0][t] + ypart3[j][1][t]
                           + ypart3[j][2][t] + ypart3[j][3][t];
                float yl = yrow[(size_t)l * D_INNER_ + t];
                float zz = zrow[(size_t)l * D_IN_PROJ_ + t];
                float yo = (yl + alf[l] * corr) * (zz / (1.f + expf(-zz)));
                yrow[(size_t)l * D_INNER_ + t] = yo;
            }
        }
        __syncthreads();
    }
}

// ---------------- launch ----------------
extern "C" void kernel_launch(void* const* d_in, const int* in_sizes, int n_in,
                              void* d_out, int out_size) {
    const float* hidden     = (const float*)d_in[0];
    const float* in_proj    = (const float*)d_in[1];
    const float* out_proj   = (const float*)d_in[2];
    const float* conv_w     = (const float*)d_in[3];
    const float* conv_b     = (const float*)d_in[4];
    const float* A_log      = (const float*)d_in[5];
    const float* Dv         = (const float*)d_in[6];
    const float* dt_bias    = (const float*)d_in[7];
    const float* norm_w     = (const float*)d_in[8];
    const float* out_norm_w = (const float*)d_in[9];
    float* out = (float*)d_out;

    cudaFuncSetAttribute(k_gemm<0>, cudaFuncAttributeMaxDynamicSharedMemorySize, GEMM_SMEM);
    cudaFuncSetAttribute(k_gemm<1>, cudaFuncAttributeMaxDynamicSharedMemorySize, GEMM_SMEM);
    cudaFuncSetAttribute(k_scan3, cudaFuncAttributeMaxDynamicSharedMemorySize, 65536);

    k_prep<<<PREP_CTAS, 256>>>(in_proj, out_proj);                                   // 1
    k_actquant<DIMX, 0><<<MROWS_, 256>>>(hidden, norm_w);                            // 2
    k_gemm<0><<<dim3((D_IN_PROJ_ + 127) / 128, MROWS_ / 128), 256, GEMM_SMEM>>>(nullptr, nullptr); // 3
    k_scan1<<<dim3(NCHUNK_, BATCH_ * NHEADS_), 256>>>(A_log, Dv, dt_bias, conv_w, conv_b);         // 4 <- captured
    k_scan2<<<BATCH_ * NHEADS_, 512>>>();                                            // 5
    k_scan3<<<dim3(NCHUNK_, BATCH_ * NHEADS_), 256, 65536>>>();                      // 6
    k_actquant<D_INNER_, 1><<<MROWS_, 256>>>(nullptr, out_norm_w);                   // 7
    k_gemm<1><<<dim3(DIMX / 128, MROWS_ / 128), 256, GEMM_SMEM>>>(hidden, out);      // 8
}

// round 13
// speedup vs baseline: 1.0166x; 1.0166x over previous
#include <cuda_runtime.h>
#include <cuda_bf16.h>
#include <cstdint>

#define DIMX      2048
#define D_STATE_  128
#define NHEADS_   64
#define HEADDIM_  64
#define D_INNER_  4096
#define D_IN_PROJ_ 8512
#define CONV_DIM_ 4352
#define BATCH_    2
#define SEQ_      2048
#define MROWS_    4096
#define DT_OFF_   8448
#define NPAD_IN_  8704
#define NCHUNK_   16
#define LCH_      128
#define PREP_CTAS 148

typedef __nv_bfloat16 bf16;
typedef unsigned long long u64;

// ---------------- device scratch ----------------
__device__ __align__(16)  float g_wpartA[PREP_CTAS];
__device__ __align__(16)  float g_wpartB[PREP_CTAS];
__device__ unsigned long long g_prep_ctr;
__device__ __align__(128) bf16  g_WqIn[(size_t)NPAD_IN_ * DIMX];
__device__ __align__(128) bf16  g_WqOut[(size_t)DIMX * D_INNER_];
__device__ __align__(128) bf16  g_Aq[(size_t)MROWS_ * DIMX];
__device__ __align__(128) bf16  g_Yq[(size_t)MROWS_ * D_INNER_];
__device__                float g_sA[MROWS_];
__device__                float g_sY[MROWS_];
__device__ __align__(128) float g_ZX[(size_t)MROWS_ * D_IN_PROJ_];
__device__ __align__(128) float g_XC[(size_t)MROWS_ * CONV_DIM_];
__device__ __align__(128) float g_Y[(size_t)MROWS_ * D_INNER_];
__device__ __align__(128) float g_alpha[(size_t)BATCH_ * NHEADS_ * SEQ_];
__device__ __align__(128) float g_S[(size_t)BATCH_ * NHEADS_ * NCHUNK_ * 8192];
__device__ __align__(128) float g_H[(size_t)BATCH_ * NHEADS_ * NCHUNK_ * 8192];

// ---------------- helpers ----------------
__device__ __forceinline__ uint32_t smem_u32(const void* p) {
    uint32_t a;
    asm("{ .reg .u64 t; cvta.to.shared.u64 t, %1; cvt.u32.u64 %0, t; }" : "=r"(a) : "l"(p));
    return a;
}
__device__ __forceinline__ u64 pk2(float lo, float hi) { u64 r; asm("mov.b64 %0, {%1,%2};" : "=l"(r) : "f"(lo), "f"(hi)); return r; }
__device__ __forceinline__ void upk2(float& lo, float& hi, u64 v) { asm("mov.b64 {%0,%1}, %2;" : "=f"(lo), "=f"(hi) : "l"(v)); }
__device__ __forceinline__ u64 fma2(u64 a, u64 b, u64 c) { u64 d; asm("fma.rn.f32x2 %0, %1, %2, %3;" : "=l"(d) : "l"(a), "l"(b), "l"(c)); return d; }
__device__ __forceinline__ u64 mul2(u64 a, u64 b) { u64 d; asm("mul.rn.f32x2 %0, %1, %2;" : "=l"(d) : "l"(a), "l"(b)); return d; }

// ---------------- block reduce ----------------
template<bool MAXOP>
__device__ __forceinline__ float blockReduce(float v) {
    __shared__ float sm[8];
    int lane = threadIdx.x & 31, wid = threadIdx.x >> 5;
    #pragma unroll
    for (int o = 16; o; o >>= 1) {
        float u = __shfl_xor_sync(0xffffffffu, v, o);
        v = MAXOP ? fmaxf(v, u) : v + u;
    }
    if (lane == 0) sm[wid] = v;
    __syncthreads();
    if (threadIdx.x < 32) {
        v = (lane < 8) ? sm[lane] : (MAXOP ? -3.4e38f : 0.f);
        #pragma unroll
        for (int o = 4; o; o >>= 1) {
            float u = __shfl_xor_sync(0xffffffffu, v, o);
            v = MAXOP ? fmaxf(v, u) : v + u;
        }
        if (lane == 0) sm[0] = v;
    }
    __syncthreads();
    v = sm[0];
    __syncthreads();
    return v;
}

// ---------------- persistent prep ----------------
#define NQ1 ((long)D_IN_PROJ_ * DIMX / 4)
#define NQ2 ((long)DIMX * D_INNER_ / 4)
#define NQP ((long)(NPAD_IN_ - D_IN_PROJ_) * DIMX / 4)
__global__ void __launch_bounds__(256) k_prep(const float* __restrict__ w1,
                                              const float* __restrict__ w2) {
    const int cta = blockIdx.x, tid = threadIdx.x;
    float s1 = 0.f, s2 = 0.f;
    for (long i = (long)cta * 256 + tid; i < NQ1; i += (long)PREP_CTAS * 256) {
        float4 v = ((const float4*)w1)[i];
        s1 += fabsf(v.x) + fabsf(v.y) + fabsf(v.z) + fabsf(v.w);
    }
    for (long i = (long)cta * 256 + tid; i < NQ2; i += (long)PREP_CTAS * 256) {
        float4 v = ((const float4*)w2)[i];
        s2 += fabsf(v.x) + fabsf(v.y) + fabsf(v.z) + fabsf(v.w);
    }
    s1 = blockReduce<false>(s1);
    s2 = blockReduce<false>(s2);
    if (tid == 0) { g_wpartA[cta] = s1; g_wpartB[cta] = s2; }

    __threadfence();
    __syncthreads();
    if (tid == 0) {
        unsigned long long old = atomicAdd(&g_prep_ctr, 1ull);
        unsigned long long target = (old / PREP_CTAS + 1ull) * PREP_CTAS;
        while (*((volatile unsigned long long*)&g_prep_ctr) < target) { }
    }
    __syncthreads();
    __threadfence();

    float a = 0.f, b = 0.f;
    for (int i = 0; i < PREP_CTAS; i++) { a += g_wpartA[i]; b += g_wpartB[i]; }
    const float sc0 = fmaxf(a / ((float)D_IN_PROJ_ * (float)DIMX), 1e-5f);
    const float sc1 = fmaxf(b / ((float)DIMX * (float)D_INNER_), 1e-5f);

    for (long q = (long)cta * 256 + tid; q < NQ1 + NQ2 + NQP; q += (long)PREP_CTAS * 256) {
        const float* w; bf16* dst; float sc; long i;
        if (q < NQ1) { w = w1; dst = g_WqIn;  sc = sc0; i = q * 4; }
        else if (q < NQ1 + NQ2) { w = w2; dst = g_WqOut; sc = sc1; i = (q - NQ1) * 4; }
        else {
            long i2 = (q - NQ1 - NQ2) * 4;
            *(uint2*)(g_WqIn + (size_t)D_IN_PROJ_ * DIMX + i2) = make_uint2(0, 0);
            continue;
        }
        float4 v = *(const float4*)(w + i);
        float vv[4] = {v.x, v.y, v.z, v.w};
        bf16 o[4];
        #pragma unroll
        for (int j = 0; j < 4; j++) {
            float ws = vv[j] / sc;
            float qq = (ws >= 0.f) ? floorf(ws + 0.5f) : ceilf(ws - 0.5f);
            o[j] = __float2bfloat16(fminf(fmaxf(qq, -1.f), 1.f));
        }
        *(uint2*)(dst + i) = *(uint2*)o;
    }
}

// ---------------- fused norms + activation quant ----------------
template<int W, int WHICH>
__global__ void k_actquant(const float* __restrict__ X, const float* __restrict__ nw) {
    constexpr int VPT = W / 1024;
    const int row = blockIdx.x, tid = threadIdx.x;
    const float4* xr = (const float4*)((WHICH ? g_Y : X) + (size_t)row * W);
    const float4* nw4 = (const float4*)nw;
    float4 x[VPT];
    float ss = 0.f;
    #pragma unroll
    for (int i = 0; i < VPT; i++) {
        x[i] = xr[tid + i * 256];
        ss += x[i].x * x[i].x + x[i].y * x[i].y + x[i].z * x[i].z + x[i].w * x[i].w;
    }
    ss = blockReduce<false>(ss);
    float r = rsqrtf(ss / (float)W + 1e-6f);
    float4 h[VPT]; float sum = 0.f, sq = 0.f;
    #pragma unroll
    for (int i = 0; i < VPT; i++) {
        float4 w4 = nw4[tid + i * 256];
        h[i].x = w4.x * x[i].x * r; h[i].y = w4.y * x[i].y * r;
        h[i].z = w4.z * x[i].z * r; h[i].w = w4.w * x[i].w * r;
        sum += h[i].x + h[i].y + h[i].z + h[i].w;
        sq  += h[i].x * h[i].x + h[i].y * h[i].y + h[i].z * h[i].z + h[i].w * h[i].w;
    }
    sum = blockReduce<false>(sum);
    sq  = blockReduce<false>(sq);
    float mean = sum / (float)W;
    float var  = sq / (float)W - mean * mean;
    float rv = rsqrtf(var + 1e-5f);
    float amax = 0.f;
    #pragma unroll
    for (int i = 0; i < VPT; i++) {
        h[i].x = (h[i].x - mean) * rv; h[i].y = (h[i].y - mean) * rv;
        h[i].z = (h[i].z - mean) * rv; h[i].w = (h[i].w - mean) * rv;
        amax = fmaxf(amax, fmaxf(fmaxf(fabsf(h[i].x), fabsf(h[i].y)),
                                 fmaxf(fabsf(h[i].z), fabsf(h[i].w))));
    }
    amax = blockReduce<true>(amax);
    float scale = 127.f / fmaxf(amax, 1e-5f);
    bf16* Q = WHICH ? g_Yq : g_Aq;
    #pragma unroll
    for (int i = 0; i < VPT; i++) {
        bf16 o[4];
        float c[4] = {h[i].x, h[i].y, h[i].z, h[i].w};
        #pragma unroll
        for (int j = 0; j < 4; j++) {
            float q = rintf(c[j] * scale);
            o[j] = __float2bfloat16(fminf(fmaxf(q, -128.f), 127.f));
        }
        *(uint2*)(Q + (size_t)row * W + (tid + i * 256) * 4) = *(uint2*)o;
    }
    if (tid == 0) (WHICH ? g_sY : g_sA)[row] = scale;
}

// ---------------- pipelined bf16 mma.sync GEMM (measured, unchanged) ------
#define BMg 128
#define BNg 128
#define BKg 32
#define LDSg 40
#define STG_ELEMS (BMg * LDSg)
#define STG_BYTES (2 * STG_ELEMS * 2)
#define GEMM_SMEM (4 * STG_BYTES)

template<int MODE>
__global__ void __launch_bounds__(256, 2) k_gemm(const float* __restrict__ resid,
                                                 float* __restrict__ outp) {
    constexpr int K = MODE ? D_INNER_ : DIMX;
    constexpr int N = MODE ? DIMX : D_IN_PROJ_;
    constexpr int NS = K / BKg;

    const bf16*  __restrict__ A  = MODE ? g_Yq : g_Aq;
    const bf16*  __restrict__ Bw = MODE ? g_WqOut : g_WqIn;
    const float* __restrict__ rs = MODE ? g_sY : g_sA;
    float*       __restrict__ C  = MODE ? outp : g_ZX;

    extern __shared__ char smem[];
    const uint32_t sb = smem_u32(smem);

    const int tid = threadIdx.x;
    const int lane = tid & 31, wid = tid >> 5;
    const int wm = wid & 1, wn = wid >> 1;
    const int m0 = blockIdx.y * BMg, n0 = blockIdx.x * BNg;
    const int mw = wm * 64, nwp = wn * 32;

    float acc[4][4][4];
    #pragma unroll
    for (int a = 0; a < 4; a++)
        #pragma unroll
        for (int b = 0; b < 4; b++)
            #pragma unroll
            for (int c = 0; c < 4; c++) acc[a][b][c] = 0.f;

    const bf16* gsrc[4];
    uint32_t sdst[4];
    #pragma unroll
    for (int i = 0; i < 4; i++) {
        int q = tid + i * 256;
        if (q < 512) {
            int row = q >> 2, c = q & 3;
            gsrc[i] = A + (size_t)(m0 + row) * K + c * 8;
            sdst[i] = (uint32_t)(row * LDSg + c * 8) * 2;
        } else {
            int qq = q - 512, row = qq >> 2, c = qq & 3;
            gsrc[i] = Bw + (size_t)(n0 + row) * K + c * 8;
            sdst[i] = (uint32_t)(STG_ELEMS + row * LDSg + c * 8) * 2;
        }
    }

    #define LOAD_STAGE(s_) do { \
        uint32_t base_ = sb + ((s_) & 3) * STG_BYTES; \
        _Pragma("unroll") \
        for (int i_ = 0; i_ < 4; i_++) \
            asm volatile("cp.async.cg.shared.global [%0], [%1], 16;" \
                :: "r"(base_ + sdst[i_]), "l"(gsrc[i_] + (s_) * BKg) : "memory"); \
        asm volatile("cp.async.commit_group;" ::: "memory"); \
    } while (0)

    uint32_t aOff[4], bOff[2];
    {
        int rA = mw + (lane & 15);
        int cA = (lane >> 4) * 8;
        #pragma unroll
        for (int fm = 0; fm < 4; fm++)
            aOff[fm] = (uint32_t)((rA + fm * 16) * LDSg + cA) * 2;
        int rB = nwp + ((lane >> 4) << 3) + (lane & 7);
        int cB = ((lane >> 3) & 1) * 8;
        #pragma unroll
        for (int fb = 0; fb < 2; fb++)
            bOff[fb] = (uint32_t)(STG_ELEMS + (rB + fb * 16) * LDSg + cB) * 2;
    }

    LOAD_STAGE(0); LOAD_STAGE(1); LOAD_STAGE(2);

    for (int s = 0; s < NS; s++) {
        asm volatile("cp.async.wait_group 2;" ::: "memory");
        __syncthreads();
        if (s + 3 < NS) LOAD_STAGE(s + 3);

        const uint32_t base = sb + (s & 3) * STG_BYTES;
        #pragma unroll
        for (int ks = 0; ks < BKg; ks += 16) {
            unsigned af[4][4], bfr[4][2];
            #pragma unroll
            for (int fm = 0; fm < 4; fm++)
                asm volatile("ldmatrix.sync.aligned.m8n8.x4.shared.b16 {%0,%1,%2,%3}, [%4];"
                    : "=r"(af[fm][0]), "=r"(af[fm][1]), "=r"(af[fm][2]), "=r"(af[fm][3])
                    : "r"(base + aOff[fm] + (uint32_t)(ks * 2)));
            #pragma unroll
            for (int fb = 0; fb < 2; fb++) {
                unsigned q0, q1, q2, q3;
                asm volatile("ldmatrix.sync.aligned.m8n8.x4.shared.b16 {%0,%1,%2,%3}, [%4];"
                    : "=r"(q0), "=r"(q1), "=r"(q2), "=r"(q3)
                    : "r"(base + bOff[fb] + (uint32_t)(ks * 2)));
                bfr[fb * 2][0] = q0; bfr[fb * 2][1] = q1;
                bfr[fb * 2 + 1][0] = q2; bfr[fb * 2 + 1][1] = q3;
            }
            #pragma unroll
            for (int fm = 0; fm < 4; fm++)
                #pragma unroll
                for (int fn = 0; fn < 4; fn++)
                    asm volatile("mma.sync.aligned.m16n8k16.row.col.f32.bf16.bf16.f32 "
                        "{%0,%1,%2,%3},{%4,%5,%6,%7},{%8,%9},{%0,%1,%2,%3};"
                        : "+f"(acc[fm][fn][0]), "+f"(acc[fm][fn][1]),
                          "+f"(acc[fm][fn][2]), "+f"(acc[fm][fn][3])
                        : "r"(af[fm][0]), "r"(af[fm][1]), "r"(af[fm][2]), "r"(af[fm][3]),
                          "r"(bfr[fn][0]), "r"(bfr[fn][1]));
        }
    }

    const int mr = m0 + mw + (lane >> 2);
    const int nc = n0 + nwp + (lane & 3) * 2;
    #pragma unroll
    for (int fm = 0; fm < 4; fm++) {
        int m = mr + fm * 16;
        float inv0 = 1.f / rs[m];
        float inv1 = 1.f / rs[m + 8];
        #pragma unroll
        for (int fn = 0; fn < 4; fn++) {
            int n = nc + fn * 8;
            if (n < N) {
                size_t o0 = (size_t)m * N + n;
                size_t o8 = (size_t)(m + 8) * N + n;
                float v0 = acc[fm][fn][0] * inv0;
                float v1 = acc[fm][fn][1] * inv0;
                float v2 = acc[fm][fn][2] * inv1;
                float v3 = acc[fm][fn][3] * inv1;
                if (MODE) {
                    v0 += resid[o0]; v1 += resid[o0 + 1];
                    v2 += resid[o8]; v3 += resid[o8 + 1];
                }
                C[o0] = v0; C[o0 + 1] = v1; C[o8] = v2; C[o8 + 1] = v3;
            }
        }
    }
    #undef LOAD_STAGE
}

// ---------------- causal conv1d + silu: sliding window (R6-measured) ------
__global__ void k_conv(const float* __restrict__ cw, const float* __restrict__ cb) {
    int c = blockIdx.x * 256 + threadIdx.x;
    if (c >= CONV_DIM_) return;
    int b = blockIdx.y >> 3;
    int s0 = (blockIdx.y & 7) * 256;
    const float* src = g_ZX + (size_t)(b * SEQ_) * D_IN_PROJ_ + D_INNER_ + c;
    float*       dst = g_XC + (size_t)(b * SEQ_) * CONV_DIM_ + c;
    const float w0 = cw[c * 4], w1 = cw[c * 4 + 1], w2 = cw[c * 4 + 2], w3 = cw[c * 4 + 3];
    const float bias = cb[c];
    float xm3 = 0.f, xm2 = 0.f, xm1 = 0.f;
    if (s0 > 0) {
        xm3 = src[(size_t)(s0 - 3) * D_IN_PROJ_];
        xm2 = src[(size_t)(s0 - 2) * D_IN_PROJ_];
        xm1 = src[(size_t)(s0 - 1) * D_IN_PROJ_];
    }
    #pragma unroll 4
    for (int l = s0; l < s0 + 256; l++) {
        float x0 = src[(size_t)l * D_IN_PROJ_];
        float acc = fmaf(w3, x0, fmaf(w2, xm1, fmaf(w1, xm2, fmaf(w0, xm3, bias))));
        dst[(size_t)l * CONV_DIM_] = acc / (1.f + expf(-acc));
        xm3 = xm2; xm2 = xm1; xm1 = x0;
    }
}

// ---------------- PASS 1: per-chunk local scan (conv pre-applied) ---------
__global__ void __launch_bounds__(512) k_scan1(const float* __restrict__ A_log,
                                               const float* __restrict__ Dv,
                                               const float* __restrict__ dt_bias) {
    const int chunk = blockIdx.x, bh = blockIdx.y;
    const int h = bh & (NHEADS_ - 1);
    const int b = bh >> 6;
    const int l0 = chunk * LCH_;
    const int t = threadIdx.x;
    const int pc = t & 63, gc = t >> 6, n0 = gc * 16;

    __shared__ __align__(16) float xs[2][4][64];
    __shared__ __align__(16) float Bsh[2][4][128], Csh[2][4][128];
    __shared__ __align__(16) float ypart[2][4][8][64];
    __shared__ float sdt[2][4], sdA[2][4];

    const float Ah   = -expf(A_log[h]);
    const float Dh   = Dv[h];
    const float bias = dt_bias[h];

    u64 h2[8];
    #pragma unroll
    for (int i = 0; i < 8; i++) h2[i] = 0ull;

    const float* gptr = nullptr;
    if      (t < 64)  gptr = g_XC + (size_t)(b * SEQ_) * CONV_DIM_ + h * 64 + t;
    else if (t < 192) gptr = g_XC + (size_t)(b * SEQ_) * CONV_DIM_ + D_INNER_ + (t - 64);
    else if (t < 320) gptr = g_XC + (size_t)(b * SEQ_) * CONV_DIM_ + D_INNER_ + D_STATE_ + (t - 192);
    else if (t == 320) gptr = g_ZX + (size_t)(b * SEQ_) * D_IN_PROJ_ + DT_OFF_ + h;
    const size_t stride = (t < 320) ? (size_t)CONV_DIM_ : (size_t)D_IN_PROJ_;

    float r[4] = {0.f, 0.f, 0.f, 0.f};
    if (gptr) {
        #pragma unroll
        for (int s = 0; s < 4; s++) r[s] = gptr[(size_t)(l0 + s) * stride];
    }
    float* yrow = g_Y + (size_t)(b * SEQ_ + l0) * D_INNER_ + h * 64;
    float* arow = g_alpha + (size_t)bh * SEQ_ + l0;
    float aprod = 1.f;

    for (int blk = 0; blk < LCH_ / 4; blk++) {
        const int p = blk & 1, q = p ^ 1;
        if (t < 64) {
            #pragma unroll
            for (int s = 0; s < 4; s++) xs[p][s][t] = r[s];
        } else if (t < 192) {
            #pragma unroll
            for (int s = 0; s < 4; s++) Bsh[p][s][t - 64] = r[s];
        } else if (t < 320) {
            #pragma unroll
            for (int s = 0; s < 4; s++) Csh[p][s][t - 192] = r[s];
        } else if (t == 320) {
            #pragma unroll
            for (int s = 0; s < 4; s++) {
                float d = r[s] + bias;
                float sp = fmaxf(d, 0.f) + log1pf(expf(-fabsf(d)));
                float dA = expf(sp * Ah);
                sdt[p][s] = sp; sdA[p][s] = dA;
                aprod *= dA; arow[4 * blk + s] = aprod;
            }
        }
        __syncthreads();

        if (blk > 0 && t < 64) {
            #pragma unroll
            for (int s = 0; s < 4; s++) {
                float ysum = 0.f;
                #pragma unroll
                for (int g = 0; g < 8; g++) ysum += ypart[q][s][g][t];
                yrow[(size_t)(4 * (blk - 1) + s) * D_INNER_ + t] = ysum + Dh * xs[q][s][t];
            }
        }

        float rn[4] = {0.f, 0.f, 0.f, 0.f};
        if (gptr && blk + 1 < LCH_ / 4) {
            #pragma unroll
            for (int s = 0; s < 4; s++)
                rn[s] = gptr[(size_t)(l0 + 4 * blk + 4 + s) * stride];
        }

        #pragma unroll
        for (int s = 0; s < 4; s++) {
            const float dA = sdA[p][s];
            const float cf = sdt[p][s] * xs[p][s][pc];
            const u64 dA2 = pk2(dA, dA);
            const u64 cf2 = pk2(cf, cf);
            const ulonglong2* Bv = (const ulonglong2*)&Bsh[p][s][n0];
            const ulonglong2* Cv = (const ulonglong2*)&Csh[p][s][n0];
            u64 y2 = 0ull;
            #pragma unroll
            for (int i = 0; i < 4; i++) {
                ulonglong2 B2 = Bv[i];
                ulonglong2 C2 = Cv[i];
                h2[2 * i]     = fma2(h2[2 * i],     dA2, mul2(cf2, B2.x));
                y2 = fma2(h2[2 * i],     C2.x, y2);
                h2[2 * i + 1] = fma2(h2[2 * i + 1], dA2, mul2(cf2, B2.y));
                y2 = fma2(h2[2 * i + 1], C2.y, y2);
            }
            float ylo, yhi; upk2(ylo, yhi, y2);
            ypart[p][s][gc][pc] = ylo + yhi;
        }

        #pragma unroll
        for (int s = 0; s < 4; s++) r[s] = rn[s];
    }
    __syncthreads();
    if (t < 64) {
        const int q = (LCH_ / 4 - 1) & 1;
        #pragma unroll
        for (int s = 0; s < 4; s++) {
            float ysum = 0.f;
            #pragma unroll
            for (int g = 0; g < 8; g++) ysum += ypart[q][s][g][t];
            yrow[(size_t)(LCH_ - 4 + s) * D_INNER_ + t] = ysum + Dh * xs[q][s][t];
        }
    }
    float* srow = g_S + ((size_t)bh * NCHUNK_ + chunk) * 8192 + (size_t)pc * 128 + n0;
    float4* s4 = (float4*)srow;
    #pragma unroll
    for (int i = 0; i < 4; i++) {
        float4 v;
        upk2(v.x, v.y, h2[2 * i]);
        upk2(v.z, v.w, h2[2 * i + 1]);
        s4[i] = v;
    }
}

// ---------------- PASS 2: chunk-state prefix ----------------
__global__ void __launch_bounds__(512) k_scan2() {
    const int bh = blockIdx.x, t = threadIdx.x;
    float4 H[4];
    #pragma unroll
    for (int i = 0; i < 4; i++) H[i] = make_float4(0.f, 0.f, 0.f, 0.f);
    for (int c = 0; c < NCHUNK_; c++) {
        if (c > 0) {
            float4* hw = (float4*)(g_H + ((size_t)bh * NCHUNK_ + c) * 8192) + t * 4;
            #pragma unroll
            for (int i = 0; i < 4; i++) hw[i] = H[i];
        }
        float P = g_alpha[(size_t)bh * SEQ_ + c * LCH_ + LCH_ - 1];
        const float4* sv = (const float4*)(g_S + ((size_t)bh * NCHUNK_ + c) * 8192) + t * 4;
        #pragma unroll
        for (int i = 0; i < 4; i++) {
            float4 s = sv[i];
            H[i].x = fmaf(P, H[i].x, s.x);
            H[i].y = fmaf(P, H[i].y, s.y);
            H[i].z = fmaf(P, H[i].z, s.z);
            H[i].w = fmaf(P, H[i].w, s.w);
        }
    }
}

// ---------------- PASS 3: correction + gating (C from g_XC) ---------------
__global__ void __launch_bounds__(512, 2) k_scan3() {
    extern __shared__ float Cs[];                 // [128][128]
    __shared__ __align__(16) float ypart3[8][8][64];
    __shared__ float alf[LCH_];

    const int chunk = blockIdx.x, bh = blockIdx.y;
    const int h = bh & (NHEADS_ - 1);
    const int b = bh >> 6;
    const int l0 = chunk * LCH_;
    const int t = threadIdx.x;
    const int pc = t & 63, gc = t >> 6, n0 = gc * 16;

    // load conv'd C block directly from g_XC (row stride CONV_DIM_, 32 f4/row)
    {
        const float* cbase = g_XC + (size_t)(b * SEQ_ + l0) * CONV_DIM_
                           + D_INNER_ + D_STATE_;
        #pragma unroll
        for (int k = 0; k < 8; k++) {
            int idx = t + k * 512;          // 0..4095
            int row = idx >> 5, c4 = idx & 31;
            ((float4*)Cs)[idx] =
                *(const float4*)(cbase + (size_t)row * CONV_DIM_ + c4 * 4);
        }
    }
    if (t < LCH_) alf[t] = g_alpha[(size_t)bh * SEQ_ + l0 + t];

    u64 H2[8];
    if (chunk > 0) {
        const float4* hv = (const float4*)(g_H + ((size_t)bh * NCHUNK_ + chunk) * 8192
                                           + (size_t)pc * 128 + n0);
        #pragma unroll
        for (int i = 0; i < 4; i++) {
            float4 v = hv[i];
            H2[2 * i]     = pk2(v.x, v.y);
            H2[2 * i + 1] = pk2(v.z, v.w);
        }
    } else {
        #pragma unroll
        for (int i = 0; i < 8; i++) H2[i] = 0ull;
    }
    __syncthreads();

    float* yrow = g_Y + (size_t)(b * SEQ_ + l0) * D_INNER_ + h * 64;
    const float* zrow = g_ZX + (size_t)(b * SEQ_ + l0) * D_IN_PROJ_ + h * 64;

    for (int lb = 0; lb < 16; lb++) {
        #pragma unroll
        for (int j = 0; j < 8; j++) {
            int l = lb * 8 + j;
            const ulonglong2* C2 = (const ulonglong2*)&Cs[l * 128 + n0];
            u64 y2 = 0ull;
            #pragma unroll
            for (int i = 0; i < 4; i++) {
                ulonglong2 c2 = C2[i];
                y2 = fma2(H2[2 * i], c2.x, y2);
                y2 = fma2(H2[2 * i + 1], c2.y, y2);
            }
            float lo, hi; upk2(lo, hi, y2);
            ypart3[j][gc][pc] = lo + hi;
        }
        __syncthreads();
        if (t < 64) {
            #pragma unroll
            for (int j = 0; j < 8; j++) {
                int l = lb * 8 + j;
                float corr = 0.f;
                #pragma unroll
                for (int g = 0; g < 8; g++) corr += ypart3[j][g][t];
                float yl = yrow[(size_t)l * D_INNER_ + t];
                float zz = zrow[(size_t)l * D_IN_PROJ_ + t];
                float yo = (yl + alf[l] * corr) * (zz / (1.f + expf(-zz)));
                yrow[(size_t)l * D_INNER_ + t] = yo;
            }
        }
        __syncthreads();
    }
}

// ---------------- launch ----------------
extern "C" void kernel_launch(void* const* d_in, const int* in_sizes, int n_in,
                              void* d_out, int out_size) {
    const float* hidden     = (const float*)d_in[0];
    const float* in_proj    = (const float*)d_in[1];
    const float* out_proj   = (const float*)d_in[2];
    const float* conv_w     = (const float*)d_in[3];
    const float* conv_b     = (const float*)d_in[4];
    const float* A_log      = (const float*)d_in[5];
    const float* Dv         = (const float*)d_in[6];
    const float* dt_bias    = (const float*)d_in[7];
    const float* norm_w     = (const float*)d_in[8];
    const float* out_norm_w = (const float*)d_in[9];
    float* out = (float*)d_out;

    cudaFuncSetAttribute(k_gemm<0>, cudaFuncAttributeMaxDynamicSharedMemorySize, GEMM_SMEM);
    cudaFuncSetAttribute(k_gemm<1>, cudaFuncAttributeMaxDynamicSharedMemorySize, GEMM_SMEM);
    cudaFuncSetAttribute(k_scan3, cudaFuncAttributeMaxDynamicSharedMemorySize, 65536);

    k_actquant<DIMX, 0><<<MROWS_, 256>>>(hidden, norm_w);                            // 1
    k_prep<<<PREP_CTAS, 256>>>(in_proj, out_proj);                                   // 2
    k_gemm<0><<<dim3((D_IN_PROJ_ + 127) / 128, MROWS_ / 128), 256, GEMM_SMEM>>>(nullptr, nullptr); // 3
    k_conv<<<dim3((CONV_DIM_ + 255) / 256, BATCH_ * 8), 256>>>(conv_w, conv_b);      // 4 <- captured
    k_scan1<<<dim3(NCHUNK_, BATCH_ * NHEADS_), 512>>>(A_log, Dv, dt_bias);           // 5
    k_scan2<<<BATCH_ * NHEADS_, 512>>>();                                            // 6
    k_scan3<<<dim3(NCHUNK_, BATCH_ * NHEADS_), 512, 65536>>>();                      // 7
    k_actquant<D_INNER_, 1><<<MROWS_, 256>>>(nullptr, out_norm_w);                   // 8
    k_gemm<1><<<dim3(DIMX / 128, MROWS_ / 128), 256, GEMM_SMEM>>>(hidden, out);      // 9
}

// round 14
// speedup vs baseline: 1.2956x; 1.2744x over previous
#include <cuda_runtime.h>
#include <cuda_bf16.h>
#include <cstdint>

#define DIMX      2048
#define D_STATE_  128
#define NHEADS_   64
#define HEADDIM_  64
#define D_INNER_  4096
#define D_IN_PROJ_ 8512
#define CONV_DIM_ 4352
#define BATCH_    2
#define SEQ_      2048
#define MROWS_    4096
#define DT_OFF_   8448
#define NPAD_IN_  8704
#define NCHUNK_   16
#define LCH_      128
#define PREP_CTAS 148

typedef __nv_bfloat16 bf16;
typedef unsigned long long u64;

// ---------------- device scratch ----------------
__device__ __align__(16)  float g_wpartA[PREP_CTAS];
__device__ __align__(16)  float g_wpartB[PREP_CTAS];
__device__ unsigned long long g_prep_ctr;
__device__ __align__(128) bf16  g_WqIn[(size_t)NPAD_IN_ * DIMX];
__device__ __align__(128) bf16  g_WqOut[(size_t)DIMX * D_INNER_];
__device__ __align__(128) bf16  g_Aq[(size_t)MROWS_ * DIMX];
__device__ __align__(128) bf16  g_Yq[(size_t)MROWS_ * D_INNER_];
__device__                float g_sA[MROWS_];
__device__                float g_sY[MROWS_];
__device__ __align__(128) float g_ZX[(size_t)MROWS_ * D_IN_PROJ_];
__device__ __align__(128) float g_XC[(size_t)MROWS_ * CONV_DIM_];
__device__ __align__(128) float g_Y[(size_t)MROWS_ * D_INNER_];
__device__ __align__(128) float g_alpha[(size_t)BATCH_ * NHEADS_ * SEQ_];
__device__ __align__(128) float g_S[(size_t)BATCH_ * NHEADS_ * NCHUNK_ * 8192];
__device__ __align__(128) float g_H[(size_t)BATCH_ * NHEADS_ * NCHUNK_ * 8192];

// ---------------- helpers ----------------
__device__ __forceinline__ uint32_t smem_u32(const void* p) {
    uint32_t a;
    asm("{ .reg .u64 t; cvta.to.shared.u64 t, %1; cvt.u32.u64 %0, t; }" : "=r"(a) : "l"(p));
    return a;
}
__device__ __forceinline__ u64 pk2(float lo, float hi) { u64 r; asm("mov.b64 %0, {%1,%2};" : "=l"(r) : "f"(lo), "f"(hi)); return r; }
__device__ __forceinline__ void upk2(float& lo, float& hi, u64 v) { asm("mov.b64 {%0,%1}, %2;" : "=f"(lo), "=f"(hi) : "l"(v)); }
__device__ __forceinline__ u64 fma2(u64 a, u64 b, u64 c) { u64 d; asm("fma.rn.f32x2 %0, %1, %2, %3;" : "=l"(d) : "l"(a), "l"(b), "l"(c)); return d; }
__device__ __forceinline__ u64 mul2(u64 a, u64 b) { u64 d; asm("mul.rn.f32x2 %0, %1, %2;" : "=l"(d) : "l"(a), "l"(b)); return d; }

// ---------------- block reduce ----------------
template<bool MAXOP>
__device__ __forceinline__ float blockReduce(float v) {
    __shared__ float sm[8];
    int lane = threadIdx.x & 31, wid = threadIdx.x >> 5;
    #pragma unroll
    for (int o = 16; o; o >>= 1) {
        float u = __shfl_xor_sync(0xffffffffu, v, o);
        v = MAXOP ? fmaxf(v, u) : v + u;
    }
    if (lane == 0) sm[wid] = v;
    __syncthreads();
    if (threadIdx.x < 32) {
        v = (lane < 8) ? sm[lane] : (MAXOP ? -3.4e38f : 0.f);
        #pragma unroll
        for (int o = 4; o; o >>= 1) {
            float u = __shfl_xor_sync(0xffffffffu, v, o);
            v = MAXOP ? fmaxf(v, u) : v + u;
        }
        if (lane == 0) sm[0] = v;
    }
    __syncthreads();
    v = sm[0];
    __syncthreads();
    return v;
}

// ---------------- persistent prep ----------------
#define NQ1 ((long)D_IN_PROJ_ * DIMX / 4)
#define NQ2 ((long)DIMX * D_INNER_ / 4)
#define NQP ((long)(NPAD_IN_ - D_IN_PROJ_) * DIMX / 4)
__global__ void __launch_bounds__(256) k_prep(const float* __restrict__ w1,
                                              const float* __restrict__ w2) {
    const int cta = blockIdx.x, tid = threadIdx.x;
    float s1 = 0.f, s2 = 0.f;
    for (long i = (long)cta * 256 + tid; i < NQ1; i += (long)PREP_CTAS * 256) {
        float4 v = ((const float4*)w1)[i];
        s1 += fabsf(v.x) + fabsf(v.y) + fabsf(v.z) + fabsf(v.w);
    }
    for (long i = (long)cta * 256 + tid; i < NQ2; i += (long)PREP_CTAS * 256) {
        float4 v = ((const float4*)w2)[i];
        s2 += fabsf(v.x) + fabsf(v.y) + fabsf(v.z) + fabsf(v.w);
    }
    s1 = blockReduce<false>(s1);
    s2 = blockReduce<false>(s2);
    if (tid == 0) { g_wpartA[cta] = s1; g_wpartB[cta] = s2; }

    __threadfence();
    __syncthreads();
    if (tid == 0) {
        unsigned long long old = atomicAdd(&g_prep_ctr, 1ull);
        unsigned long long target = (old / PREP_CTAS + 1ull) * PREP_CTAS;
        while (*((volatile unsigned long long*)&g_prep_ctr) < target) { }
    }
    __syncthreads();
    __threadfence();

    float a = 0.f, b = 0.f;
    for (int i = 0; i < PREP_CTAS; i++) { a += g_wpartA[i]; b += g_wpartB[i]; }
    const float sc0 = fmaxf(a / ((float)D_IN_PROJ_ * (float)DIMX), 1e-5f);
    const float sc1 = fmaxf(b / ((float)DIMX * (float)D_INNER_), 1e-5f);

    for (long q = (long)cta * 256 + tid; q < NQ1 + NQ2 + NQP; q += (long)PREP_CTAS * 256) {
        const float* w; bf16* dst; float sc; long i;
        if (q < NQ1) { w = w1; dst = g_WqIn;  sc = sc0; i = q * 4; }
        else if (q < NQ1 + NQ2) { w = w2; dst = g_WqOut; sc = sc1; i = (q - NQ1) * 4; }
        else {
            long i2 = (q - NQ1 - NQ2) * 4;
            *(uint2*)(g_WqIn + (size_t)D_IN_PROJ_ * DIMX + i2) = make_uint2(0, 0);
            continue;
        }
        float4 v = *(const float4*)(w + i);
        float vv[4] = {v.x, v.y, v.z, v.w};
        bf16 o[4];
        #pragma unroll
        for (int j = 0; j < 4; j++) {
            float ws = vv[j] / sc;
            float qq = (ws >= 0.f) ? floorf(ws + 0.5f) : ceilf(ws - 0.5f);
            o[j] = __float2bfloat16(fminf(fmaxf(qq, -1.f), 1.f));
        }
        *(uint2*)(dst + i) = *(uint2*)o;
    }
}

// ---------------- fused norms + activation quant ----------------
template<int W, int WHICH>
__global__ void k_actquant(const float* __restrict__ X, const float* __restrict__ nw) {
    constexpr int VPT = W / 1024;
    const int row = blockIdx.x, tid = threadIdx.x;
    const float4* xr = (const float4*)((WHICH ? g_Y : X) + (size_t)row * W);
    const float4* nw4 = (const float4*)nw;
    float4 x[VPT];
    float ss = 0.f;
    #pragma unroll
    for (int i = 0; i < VPT; i++) {
        x[i] = xr[tid + i * 256];
        ss += x[i].x * x[i].x + x[i].y * x[i].y + x[i].z * x[i].z + x[i].w * x[i].w;
    }
    ss = blockReduce<false>(ss);
    float r = rsqrtf(ss / (float)W + 1e-6f);
    float4 h[VPT]; float sum = 0.f, sq = 0.f;
    #pragma unroll
    for (int i = 0; i < VPT; i++) {
        float4 w4 = nw4[tid + i * 256];
        h[i].x = w4.x * x[i].x * r; h[i].y = w4.y * x[i].y * r;
        h[i].z = w4.z * x[i].z * r; h[i].w = w4.w * x[i].w * r;
        sum += h[i].x + h[i].y + h[i].z + h[i].w;
        sq  += h[i].x * h[i].x + h[i].y * h[i].y + h[i].z * h[i].z + h[i].w * h[i].w;
    }
    sum = blockReduce<false>(sum);
    sq  = blockReduce<false>(sq);
    float mean = sum / (float)W;
    float var  = sq / (float)W - mean * mean;
    float rv = rsqrtf(var + 1e-5f);
    float amax = 0.f;
    #pragma unroll
    for (int i = 0; i < VPT; i++) {
        h[i].x = (h[i].x - mean) * rv; h[i].y = (h[i].y - mean) * rv;
        h[i].z = (h[i].z - mean) * rv; h[i].w = (h[i].w - mean) * rv;
        amax = fmaxf(amax, fmaxf(fmaxf(fabsf(h[i].x), fabsf(h[i].y)),
                                 fmaxf(fabsf(h[i].z), fabsf(h[i].w))));
    }
    amax = blockReduce<true>(amax);
    float scale = 127.f / fmaxf(amax, 1e-5f);
    bf16* Q = WHICH ? g_Yq : g_Aq;
    #pragma unroll
    for (int i = 0; i < VPT; i++) {
        bf16 o[4];
        float c[4] = {h[i].x, h[i].y, h[i].z, h[i].w};
        #pragma unroll
        for (int j = 0; j < 4; j++) {
            float q = rintf(c[j] * scale);
            o[j] = __float2bfloat16(fminf(fmaxf(q, -128.f), 127.f));
        }
        *(uint2*)(Q + (size_t)row * W + (tid + i * 256) * 4) = *(uint2*)o;
    }
    if (tid == 0) (WHICH ? g_sY : g_sA)[row] = scale;
}

// ---------------- pipelined bf16 mma.sync GEMM (measured, unchanged) ------
#define BMg 128
#define BNg 128
#define BKg 32
#define LDSg 40
#define STG_ELEMS (BMg * LDSg)
#define STG_BYTES (2 * STG_ELEMS * 2)
#define GEMM_SMEM (4 * STG_BYTES)

template<int MODE>
__global__ void __launch_bounds__(256, 2) k_gemm(const float* __restrict__ resid,
                                                 float* __restrict__ outp) {
    constexpr int K = MODE ? D_INNER_ : DIMX;
    constexpr int N = MODE ? DIMX : D_IN_PROJ_;
    constexpr int NS = K / BKg;

    const bf16*  __restrict__ A  = MODE ? g_Yq : g_Aq;
    const bf16*  __restrict__ Bw = MODE ? g_WqOut : g_WqIn;
    const float* __restrict__ rs = MODE ? g_sY : g_sA;
    float*       __restrict__ C  = MODE ? outp : g_ZX;

    extern __shared__ char smem[];
    const uint32_t sb = smem_u32(smem);

    const int tid = threadIdx.x;
    const int lane = tid & 31, wid = tid >> 5;
    const int wm = wid & 1, wn = wid >> 1;
    const int m0 = blockIdx.y * BMg, n0 = blockIdx.x * BNg;
    const int mw = wm * 64, nwp = wn * 32;

    float acc[4][4][4];
    #pragma unroll
    for (int a = 0; a < 4; a++)
        #pragma unroll
        for (int b = 0; b < 4; b++)
            #pragma unroll
            for (int c = 0; c < 4; c++) acc[a][b][c] = 0.f;

    const bf16* gsrc[4];
    uint32_t sdst[4];
    #pragma unroll
    for (int i = 0; i < 4; i++) {
        int q = tid + i * 256;
        if (q < 512) {
            int row = q >> 2, c = q & 3;
            gsrc[i] = A + (size_t)(m0 + row) * K + c * 8;
            sdst[i] = (uint32_t)(row * LDSg + c * 8) * 2;
        } else {
            int qq = q - 512, row = qq >> 2, c = qq & 3;
            gsrc[i] = Bw + (size_t)(n0 + row) * K + c * 8;
            sdst[i] = (uint32_t)(STG_ELEMS + row * LDSg + c * 8) * 2;
        }
    }

    #define LOAD_STAGE(s_) do { \
        uint32_t base_ = sb + ((s_) & 3) * STG_BYTES; \
        _Pragma("unroll") \
        for (int i_ = 0; i_ < 4; i_++) \
            asm volatile("cp.async.cg.shared.global [%0], [%1], 16;" \
                :: "r"(base_ + sdst[i_]), "l"(gsrc[i_] + (s_) * BKg) : "memory"); \
        asm volatile("cp.async.commit_group;" ::: "memory"); \
    } while (0)

    uint32_t aOff[4], bOff[2];
    {
        int rA = mw + (lane & 15);
        int cA = (lane >> 4) * 8;
        #pragma unroll
        for (int fm = 0; fm < 4; fm++)
            aOff[fm] = (uint32_t)((rA + fm * 16) * LDSg + cA) * 2;
        int rB = nwp + ((lane >> 4) << 3) + (lane & 7);
        int cB = ((lane >> 3) & 1) * 8;
        #pragma unroll
        for (int fb = 0; fb < 2; fb++)
            bOff[fb] = (uint32_t)(STG_ELEMS + (rB + fb * 16) * LDSg + cB) * 2;
    }

    LOAD_STAGE(0); LOAD_STAGE(1); LOAD_STAGE(2);

    for (int s = 0; s < NS; s++) {
        asm volatile("cp.async.wait_group 2;" ::: "memory");
        __syncthreads();
        if (s + 3 < NS) LOAD_STAGE(s + 3);

        const uint32_t base = sb + (s & 3) * STG_BYTES;
        #pragma unroll
        for (int ks = 0; ks < BKg; ks += 16) {
            unsigned af[4][4], bfr[4][2];
            #pragma unroll
            for (int fm = 0; fm < 4; fm++)
                asm volatile("ldmatrix.sync.aligned.m8n8.x4.shared.b16 {%0,%1,%2,%3}, [%4];"
                    : "=r"(af[fm][0]), "=r"(af[fm][1]), "=r"(af[fm][2]), "=r"(af[fm][3])
                    : "r"(base + aOff[fm] + (uint32_t)(ks * 2)));
            #pragma unroll
            for (int fb = 0; fb < 2; fb++) {
                unsigned q0, q1, q2, q3;
                asm volatile("ldmatrix.sync.aligned.m8n8.x4.shared.b16 {%0,%1,%2,%3}, [%4];"
                    : "=r"(q0), "=r"(q1), "=r"(q2), "=r"(q3)
                    : "r"(base + bOff[fb] + (uint32_t)(ks * 2)));
                bfr[fb * 2][0] = q0; bfr[fb * 2][1] = q1;
                bfr[fb * 2 + 1][0] = q2; bfr[fb * 2 + 1][1] = q3;
            }
            #pragma unroll
            for (int fm = 0; fm < 4; fm++)
                #pragma unroll
                for (int fn = 0; fn < 4; fn++)
                    asm volatile("mma.sync.aligned.m16n8k16.row.col.f32.bf16.bf16.f32 "
                        "{%0,%1,%2,%3},{%4,%5,%6,%7},{%8,%9},{%0,%1,%2,%3};"
                        : "+f"(acc[fm][fn][0]), "+f"(acc[fm][fn][1]),
                          "+f"(acc[fm][fn][2]), "+f"(acc[fm][fn][3])
                        : "r"(af[fm][0]), "r"(af[fm][1]), "r"(af[fm][2]), "r"(af[fm][3]),
                          "r"(bfr[fn][0]), "r"(bfr[fn][1]));
        }
    }

    const int mr = m0 + mw + (lane >> 2);
    const int nc = n0 + nwp + (lane & 3) * 2;
    #pragma unroll
    for (int fm = 0; fm < 4; fm++) {
        int m = mr + fm * 16;
        float inv0 = 1.f / rs[m];
        float inv1 = 1.f / rs[m + 8];
        #pragma unroll
        for (int fn = 0; fn < 4; fn++) {
            int n = nc + fn * 8;
            if (n < N) {
                size_t o0 = (size_t)m * N + n;
                size_t o8 = (size_t)(m + 8) * N + n;
                float v0 = acc[fm][fn][0] * inv0;
                float v1 = acc[fm][fn][1] * inv0;
                float v2 = acc[fm][fn][2] * inv1;
                float v3 = acc[fm][fn][3] * inv1;
                if (MODE) {
                    v0 += resid[o0]; v1 += resid[o0 + 1];
                    v2 += resid[o8]; v3 += resid[o8 + 1];
                }
                C[o0] = v0; C[o0 + 1] = v1; C[o8] = v2; C[o8 + 1] = v3;
            }
        }
    }
    #undef LOAD_STAGE
}

// ---------------- causal conv1d + silu: 64 L-steps/thread, 1088 CTAs ------
__global__ void k_conv(const float* __restrict__ cw, const float* __restrict__ cb) {
    int c = blockIdx.x * 256 + threadIdx.x;
    if (c >= CONV_DIM_) return;
    int b = blockIdx.y >> 5;
    int s0 = (blockIdx.y & 31) * 64;
    const float* src = g_ZX + (size_t)(b * SEQ_) * D_IN_PROJ_ + D_INNER_ + c;
    float*       dst = g_XC + (size_t)(b * SEQ_) * CONV_DIM_ + c;
    const float w0 = cw[c * 4], w1 = cw[c * 4 + 1], w2 = cw[c * 4 + 2], w3 = cw[c * 4 + 3];
    const float bias = cb[c];
    float xm3 = 0.f, xm2 = 0.f, xm1 = 0.f;
    if (s0 > 0) {
        xm3 = src[(size_t)(s0 - 3) * D_IN_PROJ_];
        xm2 = src[(size_t)(s0 - 2) * D_IN_PROJ_];
        xm1 = src[(size_t)(s0 - 1) * D_IN_PROJ_];
    }
    #pragma unroll 8
    for (int l = s0; l < s0 + 64; l++) {
        float x0 = src[(size_t)l * D_IN_PROJ_];
        float acc = fmaf(w3, x0, fmaf(w2, xm1, fmaf(w1, xm2, fmaf(w0, xm3, bias))));
        dst[(size_t)l * CONV_DIM_] = acc / (1.f + expf(-acc));
        xm3 = xm2; xm2 = xm1; xm1 = x0;
    }
}

// ---------------- PASS 1: per-chunk local scan (conv pre-applied) ---------
__global__ void __launch_bounds__(512) k_scan1(const float* __restrict__ A_log,
                                               const float* __restrict__ Dv,
                                               const float* __restrict__ dt_bias) {
    const int chunk = blockIdx.x, bh = blockIdx.y;
    const int h = bh & (NHEADS_ - 1);
    const int b = bh >> 6;
    const int l0 = chunk * LCH_;
    const int t = threadIdx.x;
    const int pc = t & 63, gc = t >> 6, n0 = gc * 16;

    __shared__ __align__(16) float xs[2][4][64];
    __shared__ __align__(16) float Bsh[2][4][128], Csh[2][4][128];
    __shared__ __align__(16) float ypart[2][4][8][64];
    __shared__ float sdt[2][4], sdA[2][4];

    const float Ah   = -expf(A_log[h]);
    const float Dh   = Dv[h];
    const float bias = dt_bias[h];

    u64 h2[8];
    #pragma unroll
    for (int i = 0; i < 8; i++) h2[i] = 0ull;

    const float* gptr = nullptr;
    if      (t < 64)  gptr = g_XC + (size_t)(b * SEQ_) * CONV_DIM_ + h * 64 + t;
    else if (t < 192) gptr = g_XC + (size_t)(b * SEQ_) * CONV_DIM_ + D_INNER_ + (t - 64);
    else if (t < 320) gptr = g_XC + (size_t)(b * SEQ_) * CONV_DIM_ + D_INNER_ + D_STATE_ + (t - 192);
    else if (t == 320) gptr = g_ZX + (size_t)(b * SEQ_) * D_IN_PROJ_ + DT_OFF_ + h;
    const size_t stride = (t < 320) ? (size_t)CONV_DIM_ : (size_t)D_IN_PROJ_;

    float r[4] = {0.f, 0.f, 0.f, 0.f};
    if (gptr) {
        #pragma unroll
        for (int s = 0; s < 4; s++) r[s] = gptr[(size_t)(l0 + s) * stride];
    }
    float* yrow = g_Y + (size_t)(b * SEQ_ + l0) * D_INNER_ + h * 64;
    float* arow = g_alpha + (size_t)bh * SEQ_ + l0;
    float aprod = 1.f;

    for (int blk = 0; blk < LCH_ / 4; blk++) {
        const int p = blk & 1, q = p ^ 1;
        if (t < 64) {
            #pragma unroll
            for (int s = 0; s < 4; s++) xs[p][s][t] = r[s];
        } else if (t < 192) {
            #pragma unroll
            for (int s = 0; s < 4; s++) Bsh[p][s][t - 64] = r[s];
        } else if (t < 320) {
            #pragma unroll
            for (int s = 0; s < 4; s++) Csh[p][s][t - 192] = r[s];
        } else if (t == 320) {
            #pragma unroll
            for (int s = 0; s < 4; s++) {
                float d = r[s] + bias;
                float sp = fmaxf(d, 0.f) + log1pf(expf(-fabsf(d)));
                float dA = expf(sp * Ah);
                sdt[p][s] = sp; sdA[p][s] = dA;
                aprod *= dA; arow[4 * blk + s] = aprod;
            }
        }
        __syncthreads();

        // spread epilogue: 256 (s,tt) pairs over t<256
        if (blk > 0 && t < 256) {
            const int s = t >> 6, tt = t & 63;
            float ysum = 0.f;
            #pragma unroll
            for (int g = 0; g < 8; g++) ysum += ypart[q][s][g][tt];
            yrow[(size_t)(4 * (blk - 1) + s) * D_INNER_ + tt] = ysum + Dh * xs[q][s][tt];
        }

        float rn[4] = {0.f, 0.f, 0.f, 0.f};
        if (gptr && blk + 1 < LCH_ / 4) {
            #pragma unroll
            for (int s = 0; s < 4; s++)
                rn[s] = gptr[(size_t)(l0 + 4 * blk + 4 + s) * stride];
        }

        #pragma unroll
        for (int s = 0; s < 4; s++) {
            const float dA = sdA[p][s];
            const float cf = sdt[p][s] * xs[p][s][pc];
            const u64 dA2 = pk2(dA, dA);
            const u64 cf2 = pk2(cf, cf);
            const ulonglong2* Bv = (const ulonglong2*)&Bsh[p][s][n0];
            const ulonglong2* Cv = (const ulonglong2*)&Csh[p][s][n0];
            u64 y2 = 0ull;
            #pragma unroll
            for (int i = 0; i < 4; i++) {
                ulonglong2 B2 = Bv[i];
                ulonglong2 C2 = Cv[i];
                h2[2 * i]     = fma2(h2[2 * i],     dA2, mul2(cf2, B2.x));
                y2 = fma2(h2[2 * i],     C2.x, y2);
                h2[2 * i + 1] = fma2(h2[2 * i + 1], dA2, mul2(cf2, B2.y));
                y2 = fma2(h2[2 * i + 1], C2.y, y2);
            }
            float ylo, yhi; upk2(ylo, yhi, y2);
            ypart[p][s][gc][pc] = ylo + yhi;
        }

        #pragma unroll
        for (int s = 0; s < 4; s++) r[s] = rn[s];
    }
    __syncthreads();
    if (t < 256) {
        const int q = (LCH_ / 4 - 1) & 1;
        const int s = t >> 6, tt = t & 63;
        float ysum = 0.f;
        #pragma unroll
        for (int g = 0; g < 8; g++) ysum += ypart[q][s][g][tt];
        yrow[(size_t)(LCH_ - 4 + s) * D_INNER_ + tt] = ysum + Dh * xs[q][s][tt];
    }
    float* srow = g_S + ((size_t)bh * NCHUNK_ + chunk) * 8192 + (size_t)pc * 128 + n0;
    float4* s4 = (float4*)srow;
    #pragma unroll
    for (int i = 0; i < 4; i++) {
        float4 v;
        upk2(v.x, v.y, h2[2 * i]);
        upk2(v.z, v.w, h2[2 * i + 1]);
        s4[i] = v;
    }
}

// ---------------- PASS 2: chunk-state prefix ----------------
__global__ void __launch_bounds__(512) k_scan2() {
    const int bh = blockIdx.x, t = threadIdx.x;
    float4 H[4];
    #pragma unroll
    for (int i = 0; i < 4; i++) H[i] = make_float4(0.f, 0.f, 0.f, 0.f);
    for (int c = 0; c < NCHUNK_; c++) {
        if (c > 0) {
            float4* hw = (float4*)(g_H + ((size_t)bh * NCHUNK_ + c) * 8192) + t * 4;
            #pragma unroll
            for (int i = 0; i < 4; i++) hw[i] = H[i];
        }
        float P = g_alpha[(size_t)bh * SEQ_ + c * LCH_ + LCH_ - 1];
        const float4* sv = (const float4*)(g_S + ((size_t)bh * NCHUNK_ + c) * 8192) + t * 4;
        #pragma unroll
        for (int i = 0; i < 4; i++) {
            float4 s = sv[i];
            H[i].x = fmaf(P, H[i].x, s.x);
            H[i].y = fmaf(P, H[i].y, s.y);
            H[i].z = fmaf(P, H[i].z, s.z);
            H[i].w = fmaf(P, H[i].w, s.w);
        }
    }
}

// ---------------- PASS 3: correction + gating (C from g_XC) ---------------
__global__ void __launch_bounds__(512, 2) k_scan3() {
    extern __shared__ float Cs[];                 // [128][128]
    __shared__ __align__(16) float ypart3[8][8][64];
    __shared__ float alf[LCH_];

    const int chunk = blockIdx.x, bh = blockIdx.y;
    const int h = bh & (NHEADS_ - 1);
    const int b = bh >> 6;
    const int l0 = chunk * LCH_;
    const int t = threadIdx.x;
    const int pc = t & 63, gc = t >> 6, n0 = gc * 16;

    {
        const float* cbase = g_XC + (size_t)(b * SEQ_ + l0) * CONV_DIM_
                           + D_INNER_ + D_STATE_;
        #pragma unroll
        for (int k = 0; k < 8; k++) {
            int idx = t + k * 512;
            int row = idx >> 5, c4 = idx & 31;
            ((float4*)Cs)[idx] =
                *(const float4*)(cbase + (size_t)row * CONV_DIM_ + c4 * 4);
        }
    }
    if (t < LCH_) alf[t] = g_alpha[(size_t)bh * SEQ_ + l0 + t];

    u64 H2[8];
    if (chunk > 0) {
        const float4* hv = (const float4*)(g_H + ((size_t)bh * NCHUNK_ + chunk) * 8192
                                           + (size_t)pc * 128 + n0);
        #pragma unroll
        for (int i = 0; i < 4; i++) {
            float4 v = hv[i];
            H2[2 * i]     = pk2(v.x, v.y);
            H2[2 * i + 1] = pk2(v.z, v.w);
        }
    } else {
        #pragma unroll
        for (int i = 0; i < 8; i++) H2[i] = 0ull;
    }
    __syncthreads();

    float* yrow = g_Y + (size_t)(b * SEQ_ + l0) * D_INNER_ + h * 64;
    const float* zrow = g_ZX + (size_t)(b * SEQ_ + l0) * D_IN_PROJ_ + h * 64;

    for (int lb = 0; lb < 16; lb++) {
        #pragma unroll
        for (int j = 0; j < 8; j++) {
            int l = lb * 8 + j;
            const ulonglong2* C2 = (const ulonglong2*)&Cs[l * 128 + n0];
            u64 y2 = 0ull;
            #pragma unroll
            for (int i = 0; i < 4; i++) {
                ulonglong2 c2 = C2[i];
                y2 = fma2(H2[2 * i], c2.x, y2);
                y2 = fma2(H2[2 * i + 1], c2.y, y2);
            }
            float lo, hi; upk2(lo, hi, y2);
            ypart3[j][gc][pc] = lo + hi;
        }
        __syncthreads();
        if (t < 256) {
            const int j0 = (t >> 6) * 2, tt = t & 63;
            #pragma unroll
            for (int jo = 0; jo < 2; jo++) {
                int j = j0 + jo;
                int l = lb * 8 + j;
                float corr = 0.f;
                #pragma unroll
                for (int g = 0; g < 8; g++) corr += ypart3[j][g][tt];
                float yl = yrow[(size_t)l * D_INNER_ + tt];
                float zz = zrow[(size_t)l * D_IN_PROJ_ + tt];
                float yo = (yl + alf[l] * corr) * (zz / (1.f + expf(-zz)));
                yrow[(size_t)l * D_INNER_ + tt] = yo;
            }
        }
        __syncthreads();
    }
}

// ---------------- launch ----------------
extern "C" void kernel_launch(void* const* d_in, const int* in_sizes, int n_in,
                              void* d_out, int out_size) {
    const float* hidden     = (const float*)d_in[0];
    const float* in_proj    = (const float*)d_in[1];
    const float* out_proj   = (const float*)d_in[2];
    const float* conv_w     = (const float*)d_in[3];
    const float* conv_b     = (const float*)d_in[4];
    const float* A_log      = (const float*)d_in[5];
    const float* Dv         = (const float*)d_in[6];
    const float* dt_bias    = (const float*)d_in[7];
    const float* norm_w     = (const float*)d_in[8];
    const float* out_norm_w = (const float*)d_in[9];
    float* out = (float*)d_out;

    cudaFuncSetAttribute(k_gemm<0>, cudaFuncAttributeMaxDynamicSharedMemorySize, GEMM_SMEM);
    cudaFuncSetAttribute(k_gemm<1>, cudaFuncAttributeMaxDynamicSharedMemorySize, GEMM_SMEM);
    cudaFuncSetAttribute(k_scan3, cudaFuncAttributeMaxDynamicSharedMemorySize, 65536);

    k_actquant<DIMX, 0><<<MROWS_, 256>>>(hidden, norm_w);                            // 1
    k_prep<<<PREP_CTAS, 256>>>(in_proj, out_proj);                                   // 2
    k_gemm<0><<<dim3((D_IN_PROJ_ + 127) / 128, MROWS_ / 128), 256, GEMM_SMEM>>>(nullptr, nullptr); // 3
    k_conv<<<dim3((CONV_DIM_ + 255) / 256, BATCH_ * 32), 256>>>(conv_w, conv_b);     // 4 <- captured
    k_scan1<<<dim3(NCHUNK_, BATCH_ * NHEADS_), 512>>>(A_log, Dv, dt_bias);           // 5
    k_scan2<<<BATCH_ * NHEADS_, 512>>>();                                            // 6
    k_scan3<<<dim3(NCHUNK_, BATCH_ * NHEADS_), 512, 65536>>>();                      // 7
    k_actquant<D_INNER_, 1><<<MROWS_, 256>>>(nullptr, out_norm_w);                   // 8
    k_gemm<1><<<dim3(DIMX / 128, MROWS_ / 128), 256, GEMM_SMEM>>>(hidden, out);      // 9
}

// round 15
// speedup vs baseline: 1.2981x; 1.0019x over previous
#include <cuda_runtime.h>
#include <cuda_bf16.h>
#include <cstdint>

#define DIMX      2048
#define D_STATE_  128
#define NHEADS_   64
#define HEADDIM_  64
#define D_INNER_  4096
#define D_IN_PROJ_ 8512
#define CONV_DIM_ 4352
#define BATCH_    2
#define SEQ_      2048
#define MROWS_    4096
#define DT_OFF_   8448
#define NPAD_IN_  8704
#define NCHUNK_   16
#define LCH_      128
#define PREP_CTAS 148

typedef __nv_bfloat16 bf16;
typedef unsigned long long u64;

// ---------------- device scratch ----------------
__device__ __align__(16)  float g_wpartA[PREP_CTAS];
__device__ __align__(16)  float g_wpartB[PREP_CTAS];
__device__ unsigned long long g_prep_ctr;
__device__ __align__(128) bf16  g_WqIn[(size_t)NPAD_IN_ * DIMX];
__device__ __align__(128) bf16  g_WqOut[(size_t)DIMX * D_INNER_];
__device__ __align__(128) bf16  g_Aq[(size_t)MROWS_ * DIMX];
__device__ __align__(128) bf16  g_Yq[(size_t)MROWS_ * D_INNER_];
__device__                float g_sA[MROWS_];
__device__                float g_sY[MROWS_];
__device__ __align__(128) float g_ZX[(size_t)MROWS_ * D_IN_PROJ_];
__device__ __align__(128) float g_XC[(size_t)MROWS_ * CONV_DIM_];
__device__ __align__(128) float g_Y[(size_t)MROWS_ * D_INNER_];
__device__ __align__(128) float g_alpha[(size_t)BATCH_ * NHEADS_ * SEQ_];
__device__ __align__(128) float g_S[(size_t)BATCH_ * NHEADS_ * NCHUNK_ * 8192];
__device__ __align__(128) float g_H[(size_t)BATCH_ * NHEADS_ * NCHUNK_ * 8192];

// ---------------- helpers ----------------
__device__ __forceinline__ uint32_t smem_u32(const void* p) {
    uint32_t a;
    asm("{ .reg .u64 t; cvta.to.shared.u64 t, %1; cvt.u32.u64 %0, t; }" : "=r"(a) : "l"(p));
    return a;
}
__device__ __forceinline__ u64 pk2(float lo, float hi) { u64 r; asm("mov.b64 %0, {%1,%2};" : "=l"(r) : "f"(lo), "f"(hi)); return r; }
__device__ __forceinline__ void upk2(float& lo, float& hi, u64 v) { asm("mov.b64 {%0,%1}, %2;" : "=f"(lo), "=f"(hi) : "l"(v)); }
__device__ __forceinline__ u64 fma2(u64 a, u64 b, u64 c) { u64 d; asm("fma.rn.f32x2 %0, %1, %2, %3;" : "=l"(d) : "l"(a), "l"(b), "l"(c)); return d; }
__device__ __forceinline__ u64 mul2(u64 a, u64 b) { u64 d; asm("mul.rn.f32x2 %0, %1, %2;" : "=l"(d) : "l"(a), "l"(b)); return d; }

// ---------------- block reduce ----------------
template<bool MAXOP>
__device__ __forceinline__ float blockReduce(float v) {
    __shared__ float sm[8];
    int lane = threadIdx.x & 31, wid = threadIdx.x >> 5;
    #pragma unroll
    for (int o = 16; o; o >>= 1) {
        float u = __shfl_xor_sync(0xffffffffu, v, o);
        v = MAXOP ? fmaxf(v, u) : v + u;
    }
    if (lane == 0) sm[wid] = v;
    __syncthreads();
    if (threadIdx.x < 32) {
        v = (lane < 8) ? sm[lane] : (MAXOP ? -3.4e38f : 0.f);
        #pragma unroll
        for (int o = 4; o; o >>= 1) {
            float u = __shfl_xor_sync(0xffffffffu, v, o);
            v = MAXOP ? fmaxf(v, u) : v + u;
        }
        if (lane == 0) sm[0] = v;
    }
    __syncthreads();
    v = sm[0];
    __syncthreads();
    return v;
}

// per-row fused norms + act quant (256 threads), used by prep & standalone
template<int W, int WHICH>
__device__ __forceinline__ void actquant_row(const float* __restrict__ xrow,
                                             const float* __restrict__ nw,
                                             int row) {
    constexpr int VPT = W / 1024;
    const int tid = threadIdx.x;
    const float4* xr = (const float4*)xrow;
    const float4* nw4 = (const float4*)nw;
    float4 x[VPT];
    float ss = 0.f;
    #pragma unroll
    for (int i = 0; i < VPT; i++) {
        x[i] = xr[tid + i * 256];
        ss += x[i].x * x[i].x + x[i].y * x[i].y + x[i].z * x[i].z + x[i].w * x[i].w;
    }
    ss = blockReduce<false>(ss);
    float r = rsqrtf(ss / (float)W + 1e-6f);
    float4 h[VPT]; float sum = 0.f, sq = 0.f;
    #pragma unroll
    for (int i = 0; i < VPT; i++) {
        float4 w4 = nw4[tid + i * 256];
        h[i].x = w4.x * x[i].x * r; h[i].y = w4.y * x[i].y * r;
        h[i].z = w4.z * x[i].z * r; h[i].w = w4.w * x[i].w * r;
        sum += h[i].x + h[i].y + h[i].z + h[i].w;
        sq  += h[i].x * h[i].x + h[i].y * h[i].y + h[i].z * h[i].z + h[i].w * h[i].w;
    }
    sum = blockReduce<false>(sum);
    sq  = blockReduce<false>(sq);
    float mean = sum / (float)W;
    float var  = sq / (float)W - mean * mean;
    float rv = rsqrtf(var + 1e-5f);
    float amax = 0.f;
    #pragma unroll
    for (int i = 0; i < VPT; i++) {
        h[i].x = (h[i].x - mean) * rv; h[i].y = (h[i].y - mean) * rv;
        h[i].z = (h[i].z - mean) * rv; h[i].w = (h[i].w - mean) * rv;
        amax = fmaxf(amax, fmaxf(fmaxf(fabsf(h[i].x), fabsf(h[i].y)),
                                 fmaxf(fabsf(h[i].z), fabsf(h[i].w))));
    }
    amax = blockReduce<true>(amax);
    float scale = 127.f / fmaxf(amax, 1e-5f);
    bf16* Q = WHICH ? g_Yq : g_Aq;
    #pragma unroll
    for (int i = 0; i < VPT; i++) {
        bf16 o[4];
        float c[4] = {h[i].x, h[i].y, h[i].z, h[i].w};
        #pragma unroll
        for (int j = 0; j < 4; j++) {
            float q = rintf(c[j] * scale);
            o[j] = __float2bfloat16(fminf(fmaxf(q, -128.f), 127.f));
        }
        *(uint2*)(Q + (size_t)row * W + (tid + i * 256) * 4) = *(uint2*)o;
    }
    if (tid == 0) (WHICH ? g_sY : g_sA)[row] = scale;
}

// ---------------- persistent prep: actquant0 + |w| reduce + quantize ------
#define NQ1 ((long)D_IN_PROJ_ * DIMX / 4)
#define NQ2 ((long)DIMX * D_INNER_ / 4)
#define NQP ((long)(NPAD_IN_ - D_IN_PROJ_) * DIMX / 4)
__global__ void __launch_bounds__(256) k_prep(const float* __restrict__ w1,
                                              const float* __restrict__ w2,
                                              const float* __restrict__ hidden,
                                              const float* __restrict__ norm_w) {
    const int cta = blockIdx.x, tid = threadIdx.x;

    // phase 0: activation quant of hidden (independent of weights)
    for (int row = cta; row < MROWS_; row += PREP_CTAS)
        actquant_row<DIMX, 0>(hidden + (size_t)row * DIMX, norm_w, row);

    // phase 1: partial |w| sums
    float s1 = 0.f, s2 = 0.f;
    for (long i = (long)cta * 256 + tid; i < NQ1; i += (long)PREP_CTAS * 256) {
        float4 v = ((const float4*)w1)[i];
        s1 += fabsf(v.x) + fabsf(v.y) + fabsf(v.z) + fabsf(v.w);
    }
    for (long i = (long)cta * 256 + tid; i < NQ2; i += (long)PREP_CTAS * 256) {
        float4 v = ((const float4*)w2)[i];
        s2 += fabsf(v.x) + fabsf(v.y) + fabsf(v.z) + fabsf(v.w);
    }
    s1 = blockReduce<false>(s1);
    s2 = blockReduce<false>(s2);
    if (tid == 0) { g_wpartA[cta] = s1; g_wpartB[cta] = s2; }

    __threadfence();
    __syncthreads();
    if (tid == 0) {
        unsigned long long old = atomicAdd(&g_prep_ctr, 1ull);
        unsigned long long target = (old / PREP_CTAS + 1ull) * PREP_CTAS;
        while (*((volatile unsigned long long*)&g_prep_ctr) < target) { }
    }
    __syncthreads();
    __threadfence();

    float a = 0.f, b = 0.f;
    for (int i = 0; i < PREP_CTAS; i++) { a += g_wpartA[i]; b += g_wpartB[i]; }
    const float sc0 = fmaxf(a / ((float)D_IN_PROJ_ * (float)DIMX), 1e-5f);
    const float sc1 = fmaxf(b / ((float)DIMX * (float)D_INNER_), 1e-5f);

    for (long q = (long)cta * 256 + tid; q < NQ1 + NQ2 + NQP; q += (long)PREP_CTAS * 256) {
        const float* w; bf16* dst; float sc; long i;
        if (q < NQ1) { w = w1; dst = g_WqIn;  sc = sc0; i = q * 4; }
        else if (q < NQ1 + NQ2) { w = w2; dst = g_WqOut; sc = sc1; i = (q - NQ1) * 4; }
        else {
            long i2 = (q - NQ1 - NQ2) * 4;
            *(uint2*)(g_WqIn + (size_t)D_IN_PROJ_ * DIMX + i2) = make_uint2(0, 0);
            continue;
        }
        float4 v = *(const float4*)(w + i);
        float vv[4] = {v.x, v.y, v.z, v.w};
        bf16 o[4];
        #pragma unroll
        for (int j = 0; j < 4; j++) {
            float ws = vv[j] / sc;
            float qq = (ws >= 0.f) ? floorf(ws + 0.5f) : ceilf(ws - 0.5f);
            o[j] = __float2bfloat16(fminf(fmaxf(qq, -1.f), 1.f));
        }
        *(uint2*)(dst + i) = *(uint2*)o;
    }
}

// ---------------- standalone actquant (for Y -> Yq) ----------------
template<int W, int WHICH>
__global__ void k_actquant(const float* __restrict__ X, const float* __restrict__ nw) {
    const int row = blockIdx.x;
    actquant_row<W, WHICH>((WHICH ? g_Y : X) + (size_t)row * W, nw, row);
}

// ---------------- pipelined bf16 mma.sync GEMM (measured, unchanged) ------
#define BMg 128
#define BNg 128
#define BKg 32
#define LDSg 40
#define STG_ELEMS (BMg * LDSg)
#define STG_BYTES (2 * STG_ELEMS * 2)
#define GEMM_SMEM (4 * STG_BYTES)

template<int MODE>
__global__ void __launch_bounds__(256, 2) k_gemm(const float* __restrict__ resid,
                                                 float* __restrict__ outp) {
    constexpr int K = MODE ? D_INNER_ : DIMX;
    constexpr int N = MODE ? DIMX : D_IN_PROJ_;
    constexpr int NS = K / BKg;

    const bf16*  __restrict__ A  = MODE ? g_Yq : g_Aq;
    const bf16*  __restrict__ Bw = MODE ? g_WqOut : g_WqIn;
    const float* __restrict__ rs = MODE ? g_sY : g_sA;
    float*       __restrict__ C  = MODE ? outp : g_ZX;

    extern __shared__ char smem[];
    const uint32_t sb = smem_u32(smem);

    const int tid = threadIdx.x;
    const int lane = tid & 31, wid = tid >> 5;
    const int wm = wid & 1, wn = wid >> 1;
    const int m0 = blockIdx.y * BMg, n0 = blockIdx.x * BNg;
    const int mw = wm * 64, nwp = wn * 32;

    float acc[4][4][4];
    #pragma unroll
    for (int a = 0; a < 4; a++)
        #pragma unroll
        for (int b = 0; b < 4; b++)
            #pragma unroll
            for (int c = 0; c < 4; c++) acc[a][b][c] = 0.f;

    const bf16* gsrc[4];
    uint32_t sdst[4];
    #pragma unroll
    for (int i = 0; i < 4; i++) {
        int q = tid + i * 256;
        if (q < 512) {
            int row = q >> 2, c = q & 3;
            gsrc[i] = A + (size_t)(m0 + row) * K + c * 8;
            sdst[i] = (uint32_t)(row * LDSg + c * 8) * 2;
        } else {
            int qq = q - 512, row = qq >> 2, c = qq & 3;
            gsrc[i] = Bw + (size_t)(n0 + row) * K + c * 8;
            sdst[i] = (uint32_t)(STG_ELEMS + row * LDSg + c * 8) * 2;
        }
    }

    #define LOAD_STAGE(s_) do { \
        uint32_t base_ = sb + ((s_) & 3) * STG_BYTES; \
        _Pragma("unroll") \
        for (int i_ = 0; i_ < 4; i_++) \
            asm volatile("cp.async.cg.shared.global [%0], [%1], 16;" \
                :: "r"(base_ + sdst[i_]), "l"(gsrc[i_] + (s_) * BKg) : "memory"); \
        asm volatile("cp.async.commit_group;" ::: "memory"); \
    } while (0)

    uint32_t aOff[4], bOff[2];
    {
        int rA = mw + (lane & 15);
        int cA = (lane >> 4) * 8;
        #pragma unroll
        for (int fm = 0; fm < 4; fm++)
            aOff[fm] = (uint32_t)((rA + fm * 16) * LDSg + cA) * 2;
        int rB = nwp + ((lane >> 4) << 3) + (lane & 7);
        int cB = ((lane >> 3) & 1) * 8;
        #pragma unroll
        for (int fb = 0; fb < 2; fb++)
            bOff[fb] = (uint32_t)(STG_ELEMS + (rB + fb * 16) * LDSg + cB) * 2;
    }

    LOAD_STAGE(0); LOAD_STAGE(1); LOAD_STAGE(2);

    for (int s = 0; s < NS; s++) {
        asm volatile("cp.async.wait_group 2;" ::: "memory");
        __syncthreads();
        if (s + 3 < NS) LOAD_STAGE(s + 3);

        const uint32_t base = sb + (s & 3) * STG_BYTES;
        #pragma unroll
        for (int ks = 0; ks < BKg; ks += 16) {
            unsigned af[4][4], bfr[4][2];
            #pragma unroll
            for (int fm = 0; fm < 4; fm++)
                asm volatile("ldmatrix.sync.aligned.m8n8.x4.shared.b16 {%0,%1,%2,%3}, [%4];"
                    : "=r"(af[fm][0]), "=r"(af[fm][1]), "=r"(af[fm][2]), "=r"(af[fm][3])
                    : "r"(base + aOff[fm] + (uint32_t)(ks * 2)));
            #pragma unroll
            for (int fb = 0; fb < 2; fb++) {
                unsigned q0, q1, q2, q3;
                asm volatile("ldmatrix.sync.aligned.m8n8.x4.shared.b16 {%0,%1,%2,%3}, [%4];"
                    : "=r"(q0), "=r"(q1), "=r"(q2), "=r"(q3)
                    : "r"(base + bOff[fb] + (uint32_t)(ks * 2)));
                bfr[fb * 2][0] = q0; bfr[fb * 2][1] = q1;
                bfr[fb * 2 + 1][0] = q2; bfr[fb * 2 + 1][1] = q3;
            }
            #pragma unroll
            for (int fm = 0; fm < 4; fm++)
                #pragma unroll
                for (int fn = 0; fn < 4; fn++)
                    asm volatile("mma.sync.aligned.m16n8k16.row.col.f32.bf16.bf16.f32 "
                        "{%0,%1,%2,%3},{%4,%5,%6,%7},{%8,%9},{%0,%1,%2,%3};"
                        : "+f"(acc[fm][fn][0]), "+f"(acc[fm][fn][1]),
                          "+f"(acc[fm][fn][2]), "+f"(acc[fm][fn][3])
                        : "r"(af[fm][0]), "r"(af[fm][1]), "r"(af[fm][2]), "r"(af[fm][3]),
                          "r"(bfr[fn][0]), "r"(bfr[fn][1]));
        }
    }

    const int mr = m0 + mw + (lane >> 2);
    const int nc = n0 + nwp + (lane & 3) * 2;
    #pragma unroll
    for (int fm = 0; fm < 4; fm++) {
        int m = mr + fm * 16;
        float inv0 = 1.f / rs[m];
        float inv1 = 1.f / rs[m + 8];
        #pragma unroll
        for (int fn = 0; fn < 4; fn++) {
            int n = nc + fn * 8;
            if (n < N) {
                size_t o0 = (size_t)m * N + n;
                size_t o8 = (size_t)(m + 8) * N + n;
                float v0 = acc[fm][fn][0] * inv0;
                float v1 = acc[fm][fn][1] * inv0;
                float v2 = acc[fm][fn][2] * inv1;
                float v3 = acc[fm][fn][3] * inv1;
                if (MODE) {
                    v0 += resid[o0]; v1 += resid[o0 + 1];
                    v2 += resid[o8]; v3 += resid[o8 + 1];
                }
                C[o0] = v0; C[o0 + 1] = v1; C[o8] = v2; C[o8 + 1] = v3;
            }
        }
    }
    #undef LOAD_STAGE
}

// ---------------- causal conv1d + silu ----------------
__global__ void k_conv(const float* __restrict__ cw, const float* __restrict__ cb) {
    int c = blockIdx.x * 256 + threadIdx.x;
    if (c >= CONV_DIM_) return;
    int b = blockIdx.y >> 5;
    int s0 = (blockIdx.y & 31) * 64;
    const float* src = g_ZX + (size_t)(b * SEQ_) * D_IN_PROJ_ + D_INNER_ + c;
    float*       dst = g_XC + (size_t)(b * SEQ_) * CONV_DIM_ + c;
    const float w0 = cw[c * 4], w1 = cw[c * 4 + 1], w2 = cw[c * 4 + 2], w3 = cw[c * 4 + 3];
    const float bias = cb[c];
    float xm3 = 0.f, xm2 = 0.f, xm1 = 0.f;
    if (s0 > 0) {
        xm3 = src[(size_t)(s0 - 3) * D_IN_PROJ_];
        xm2 = src[(size_t)(s0 - 2) * D_IN_PROJ_];
        xm1 = src[(size_t)(s0 - 1) * D_IN_PROJ_];
    }
    #pragma unroll 8
    for (int l = s0; l < s0 + 64; l++) {
        float x0 = src[(size_t)l * D_IN_PROJ_];
        float acc = fmaf(w3, x0, fmaf(w2, xm1, fmaf(w1, xm2, fmaf(w0, xm3, bias))));
        dst[(size_t)l * CONV_DIM_] = acc / (1.f + expf(-acc));
        xm3 = xm2; xm2 = xm1; xm1 = x0;
    }
}

// ---------------- PASS 1: per-chunk local scan ----------------
__global__ void __launch_bounds__(512) k_scan1(const float* __restrict__ A_log,
                                               const float* __restrict__ Dv,
                                               const float* __restrict__ dt_bias) {
    const int chunk = blockIdx.x, bh = blockIdx.y;
    const int h = bh & (NHEADS_ - 1);
    const int b = bh >> 6;
    const int l0 = chunk * LCH_;
    const int t = threadIdx.x;
    const int pc = t & 63, gc = t >> 6, n0 = gc * 16;

    __shared__ __align__(16) float xs[2][4][64];
    __shared__ __align__(16) float Bsh[2][4][128], Csh[2][4][128];
    __shared__ __align__(16) float ypart[2][4][8][64];
    __shared__ float sdt[2][4], sdA[2][4];

    const float Ah   = -expf(A_log[h]);
    const float Dh   = Dv[h];
    const float bias = dt_bias[h];

    u64 h2[8];
    #pragma unroll
    for (int i = 0; i < 8; i++) h2[i] = 0ull;

    const float* gptr = nullptr;
    if      (t < 64)  gptr = g_XC + (size_t)(b * SEQ_) * CONV_DIM_ + h * 64 + t;
    else if (t < 192) gptr = g_XC + (size_t)(b * SEQ_) * CONV_DIM_ + D_INNER_ + (t - 64);
    else if (t < 320) gptr = g_XC + (size_t)(b * SEQ_) * CONV_DIM_ + D_INNER_ + D_STATE_ + (t - 192);
    else if (t == 320) gptr = g_ZX + (size_t)(b * SEQ_) * D_IN_PROJ_ + DT_OFF_ + h;
    const size_t stride = (t < 320) ? (size_t)CONV_DIM_ : (size_t)D_IN_PROJ_;

    float r[4] = {0.f, 0.f, 0.f, 0.f};
    if (gptr) {
        #pragma unroll
        for (int s = 0; s < 4; s++) r[s] = gptr[(size_t)(l0 + s) * stride];
    }
    float* yrow = g_Y + (size_t)(b * SEQ_ + l0) * D_INNER_ + h * 64;
    float* arow = g_alpha + (size_t)bh * SEQ_ + l0;
    float aprod = 1.f;

    for (int blk = 0; blk < LCH_ / 4; blk++) {
        const int p = blk & 1, q = p ^ 1;
        if (t < 64) {
            #pragma unroll
            for (int s = 0; s < 4; s++) xs[p][s][t] = r[s];
        } else if (t < 192) {
            #pragma unroll
            for (int s = 0; s < 4; s++) Bsh[p][s][t - 64] = r[s];
        } else if (t < 320) {
            #pragma unroll
            for (int s = 0; s < 4; s++) Csh[p][s][t - 192] = r[s];
        } else if (t == 320) {
            #pragma unroll
            for (int s = 0; s < 4; s++) {
                float d = r[s] + bias;
                float sp = fmaxf(d, 0.f) + log1pf(expf(-fabsf(d)));
                float dA = expf(sp * Ah);
                sdt[p][s] = sp; sdA[p][s] = dA;
                aprod *= dA; arow[4 * blk + s] = aprod;
            }
        }
        __syncthreads();

        if (blk > 0 && t < 256) {
            const int s = t >> 6, tt = t & 63;
            float ysum = 0.f;
            #pragma unroll
            for (int g = 0; g < 8; g++) ysum += ypart[q][s][g][tt];
            yrow[(size_t)(4 * (blk - 1) + s) * D_INNER_ + tt] = ysum + Dh * xs[q][s][tt];
        }

        float rn[4] = {0.f, 0.f, 0.f, 0.f};
        if (gptr && blk + 1 < LCH_ / 4) {
            #pragma unroll
            for (int s = 0; s < 4; s++)
                rn[s] = gptr[(size_t)(l0 + 4 * blk + 4 + s) * stride];
        }

        #pragma unroll
        for (int s = 0; s < 4; s++) {
            const float dA = sdA[p][s];
            const float cf = sdt[p][s] * xs[p][s][pc];
            const u64 dA2 = pk2(dA, dA);
            const u64 cf2 = pk2(cf, cf);
            const ulonglong2* Bv = (const ulonglong2*)&Bsh[p][s][n0];
            const ulonglong2* Cv = (const ulonglong2*)&Csh[p][s][n0];
            u64 y2a = 0ull, y2b = 0ull;
            #pragma unroll
            for (int i = 0; i < 4; i++) {
                ulonglong2 B2 = Bv[i];
                ulonglong2 C2 = Cv[i];
                h2[2 * i]     = fma2(h2[2 * i],     dA2, mul2(cf2, B2.x));
                y2a = fma2(h2[2 * i],     C2.x, y2a);
                h2[2 * i + 1] = fma2(h2[2 * i + 1], dA2, mul2(cf2, B2.y));
                y2b = fma2(h2[2 * i + 1], C2.y, y2b);
            }
            float la, ha, lb, hb;
            upk2(la, ha, y2a); upk2(lb, hb, y2b);
            ypart[p][s][gc][pc] = (la + ha) + (lb + hb);
        }

        #pragma unroll
        for (int s = 0; s < 4; s++) r[s] = rn[s];
    }
    __syncthreads();
    if (t < 256) {
        const int q = (LCH_ / 4 - 1) & 1;
        const int s = t >> 6, tt = t & 63;
        float ysum = 0.f;
        #pragma unroll
        for (int g = 0; g < 8; g++) ysum += ypart[q][s][g][tt];
        yrow[(size_t)(LCH_ - 4 + s) * D_INNER_ + tt] = ysum + Dh * xs[q][s][tt];
    }
    float* srow = g_S + ((size_t)bh * NCHUNK_ + chunk) * 8192 + (size_t)pc * 128 + n0;
    float4* s4 = (float4*)srow;
    #pragma unroll
    for (int i = 0; i < 4; i++) {
        float4 v;
        upk2(v.x, v.y, h2[2 * i]);
        upk2(v.z, v.w, h2[2 * i + 1]);
        s4[i] = v;
    }
}

// ---------------- PASS 2: chunk-state prefix ----------------
__global__ void __launch_bounds__(512) k_scan2() {
    const int bh = blockIdx.x, t = threadIdx.x;
    float4 H[4];
    #pragma unroll
    for (int i = 0; i < 4; i++) H[i] = make_float4(0.f, 0.f, 0.f, 0.f);
    for (int c = 0; c < NCHUNK_; c++) {
        if (c > 0) {
            float4* hw = (float4*)(g_H + ((size_t)bh * NCHUNK_ + c) * 8192) + t * 4;
            #pragma unroll
            for (int i = 0; i < 4; i++) hw[i] = H[i];
        }
        float P = g_alpha[(size_t)bh * SEQ_ + c * LCH_ + LCH_ - 1];
        const float4* sv = (const float4*)(g_S + ((size_t)bh * NCHUNK_ + c) * 8192) + t * 4;
        #pragma unroll
        for (int i = 0; i < 4; i++) {
            float4 s = sv[i];
            H[i].x = fmaf(P, H[i].x, s.x);
            H[i].y = fmaf(P, H[i].y, s.y);
            H[i].z = fmaf(P, H[i].z, s.z);
            H[i].w = fmaf(P, H[i].w, s.w);
        }
    }
}

// ---------------- PASS 3: correction + gating ----------------
__global__ void __launch_bounds__(512, 2) k_scan3() {
    extern __shared__ float Cs[];
    __shared__ __align__(16) float ypart3[8][8][64];
    __shared__ float alf[LCH_];

    const int chunk = blockIdx.x, bh = blockIdx.y;
    const int h = bh & (NHEADS_ - 1);
    const int b = bh >> 6;
    const int l0 = chunk * LCH_;
    const int t = threadIdx.x;
    const int pc = t & 63, gc = t >> 6, n0 = gc * 16;

    {
        const float* cbase = g_XC + (size_t)(b * SEQ_ + l0) * CONV_DIM_
                           + D_INNER_ + D_STATE_;
        #pragma unroll
        for (int k = 0; k < 8; k++) {
            int idx = t + k * 512;
            int row = idx >> 5, c4 = idx & 31;
            ((float4*)Cs)[idx] =
                *(const float4*)(cbase + (size_t)row * CONV_DIM_ + c4 * 4);
        }
    }
    if (t < LCH_) alf[t] = g_alpha[(size_t)bh * SEQ_ + l0 + t];

    u64 H2[8];
    if (chunk > 0) {
        const float4* hv = (const float4*)(g_H + ((size_t)bh * NCHUNK_ + chunk) * 8192
                                           + (size_t)pc * 128 + n0);
        #pragma unroll
        for (int i = 0; i < 4; i++) {
            float4 v = hv[i];
            H2[2 * i]     = pk2(v.x, v.y);
            H2[2 * i + 1] = pk2(v.z, v.w);
        }
    } else {
        #pragma unroll
        for (int i = 0; i < 8; i++) H2[i] = 0ull;
    }
    __syncthreads();

    float* yrow = g_Y + (size_t)(b * SEQ_ + l0) * D_INNER_ + h * 64;
    const float* zrow = g_ZX + (size_t)(b * SEQ_ + l0) * D_IN_PROJ_ + h * 64;

    for (int lb = 0; lb < 16; lb++) {
        #pragma unroll
        for (int j = 0; j < 8; j++) {
            int l = lb * 8 + j;
            const ulonglong2* C2 = (const ulonglong2*)&Cs[l * 128 + n0];
            u64 y2 = 0ull;
            #pragma unroll
            for (int i = 0; i < 4; i++) {
                ulonglong2 c2 = C2[i];
                y2 = fma2(H2[2 * i], c2.x, y2);
                y2 = fma2(H2[2 * i + 1], c2.y, y2);
            }
            float lo, hi; upk2(lo, hi, y2);
            ypart3[j][gc][pc] = lo + hi;
        }
        __syncthreads();
        if (t < 256) {
            const int j0 = (t >> 6) * 2, tt = t & 63;
            #pragma unroll
            for (int jo = 0; jo < 2; jo++) {
                int j = j0 + jo;
                int l = lb * 8 + j;
                float corr = 0.f;
                #pragma unroll
                for (int g = 0; g < 8; g++) corr += ypart3[j][g][tt];
                float yl = yrow[(size_t)l * D_INNER_ + tt];
                float zz = zrow[(size_t)l * D_IN_PROJ_ + tt];
                float yo = (yl + alf[l] * corr) * (zz / (1.f + expf(-zz)));
                yrow[(size_t)l * D_INNER_ + tt] = yo;
            }
        }
        __syncthreads();
    }
}

// ---------------- launch ----------------
extern "C" void kernel_launch(void* const* d_in, const int* in_sizes, int n_in,
                              void* d_out, int out_size) {
    const float* hidden     = (const float*)d_in[0];
    const float* in_proj    = (const float*)d_in[1];
    const float* out_proj   = (const float*)d_in[2];
    const float* conv_w     = (const float*)d_in[3];
    const float* conv_b     = (const float*)d_in[4];
    const float* A_log      = (const float*)d_in[5];
    const float* Dv         = (const float*)d_in[6];
    const float* dt_bias    = (const float*)d_in[7];
    const float* norm_w     = (const float*)d_in[8];
    const float* out_norm_w = (const float*)d_in[9];
    float* out = (float*)d_out;

    cudaFuncSetAttribute(k_gemm<0>, cudaFuncAttributeMaxDynamicSharedMemorySize, GEMM_SMEM);
    cudaFuncSetAttribute(k_gemm<1>, cudaFuncAttributeMaxDynamicSharedMemorySize, GEMM_SMEM);
    cudaFuncSetAttribute(k_scan3, cudaFuncAttributeMaxDynamicSharedMemorySize, 65536);

    k_prep<<<PREP_CTAS, 256>>>(in_proj, out_proj, hidden, norm_w);                   // 1
    k_gemm<0><<<dim3((D_IN_PROJ_ + 127) / 128, MROWS_ / 128), 256, GEMM_SMEM>>>(nullptr, nullptr); // 2
    k_conv<<<dim3((CONV_DIM_ + 255) / 256, BATCH_ * 32), 256>>>(conv_w, conv_b);     // 3
    k_scan1<<<dim3(NCHUNK_, BATCH_ * NHEADS_), 512>>>(A_log, Dv, dt_bias);           // 4 <- captured
    k_scan2<<<BATCH_ * NHEADS_, 512>>>();                                            // 5
    k_scan3<<<dim3(NCHUNK_, BATCH_ * NHEADS_), 512, 65536>>>();                      // 6
    k_actquant<D_INNER_, 1><<<MROWS_, 256>>>(nullptr, out_norm_w);                   // 7
    k_gemm<1><<<dim3(DIMX / 128, MROWS_ / 128), 256, GEMM_SMEM>>>(hidden, out);      // 8
}

// round 16
// speedup vs baseline: 1.3656x; 1.0521x over previous
#include <cuda_runtime.h>
#include <cuda_bf16.h>
#include <cstdint>

#define DIMX      2048
#define D_STATE_  128
#define NHEADS_   64
#define HEADDIM_  64
#define D_INNER_  4096
#define D_IN_PROJ_ 8512
#define CONV_DIM_ 4352
#define BATCH_    2
#define SEQ_      2048
#define MROWS_    4096
#define DT_OFF_   8448
#define NPAD_IN_  8704
#define NCHUNK_   16
#define LCH_      128
#define PREP_CTAS 148

typedef __nv_bfloat16 bf16;
typedef unsigned long long u64;

// ---------------- device scratch ----------------
__device__ __align__(16)  float g_wpartA[PREP_CTAS];
__device__ __align__(16)  float g_wpartB[PREP_CTAS];
__device__ unsigned long long g_prep_ctr;
__device__ __align__(128) bf16  g_WqIn[(size_t)NPAD_IN_ * DIMX];
__device__ __align__(128) bf16  g_WqOut[(size_t)DIMX * D_INNER_];
__device__ __align__(128) bf16  g_Aq[(size_t)MROWS_ * DIMX];
__device__ __align__(128) bf16  g_Yq[(size_t)MROWS_ * D_INNER_];
__device__                float g_sA[MROWS_];
__device__                float g_sY[MROWS_];
__device__ __align__(128) float g_ZX[(size_t)MROWS_ * D_IN_PROJ_];
__device__ __align__(128) float g_XC[(size_t)MROWS_ * CONV_DIM_];
__device__ __align__(128) float g_Y[(size_t)MROWS_ * D_INNER_];
__device__ __align__(128) float g_alpha[(size_t)BATCH_ * NHEADS_ * SEQ_];
__device__ __align__(128) float g_S[(size_t)BATCH_ * NHEADS_ * NCHUNK_ * 8192];
__device__ __align__(128) float g_H[(size_t)BATCH_ * NHEADS_ * NCHUNK_ * 8192];

// ---------------- helpers ----------------
__device__ __forceinline__ uint32_t smem_u32(const void* p) {
    uint32_t a;
    asm("{ .reg .u64 t; cvta.to.shared.u64 t, %1; cvt.u32.u64 %0, t; }" : "=r"(a) : "l"(p));
    return a;
}
__device__ __forceinline__ u64 pk2(float lo, float hi) { u64 r; asm("mov.b64 %0, {%1,%2};" : "=l"(r) : "f"(lo), "f"(hi)); return r; }
__device__ __forceinline__ void upk2(float& lo, float& hi, u64 v) { asm("mov.b64 {%0,%1}, %2;" : "=f"(lo), "=f"(hi) : "l"(v)); }
__device__ __forceinline__ u64 fma2(u64 a, u64 b, u64 c) { u64 d; asm("fma.rn.f32x2 %0, %1, %2, %3;" : "=l"(d) : "l"(a), "l"(b), "l"(c)); return d; }
__device__ __forceinline__ u64 mul2(u64 a, u64 b) { u64 d; asm("mul.rn.f32x2 %0, %1, %2;" : "=l"(d) : "l"(a), "l"(b)); return d; }

// ---------------- block reduce ----------------
template<bool MAXOP>
__device__ __forceinline__ float blockReduce(float v) {
    __shared__ float sm[8];
    int lane = threadIdx.x & 31, wid = threadIdx.x >> 5;
    #pragma unroll
    for (int o = 16; o; o >>= 1) {
        float u = __shfl_xor_sync(0xffffffffu, v, o);
        v = MAXOP ? fmaxf(v, u) : v + u;
    }
    if (lane == 0) sm[wid] = v;
    __syncthreads();
    if (threadIdx.x < 32) {
        v = (lane < 8) ? sm[lane] : (MAXOP ? -3.4e38f : 0.f);
        #pragma unroll
        for (int o = 4; o; o >>= 1) {
            float u = __shfl_xor_sync(0xffffffffu, v, o);
            v = MAXOP ? fmaxf(v, u) : v + u;
        }
        if (lane == 0) sm[0] = v;
    }
    __syncthreads();
    v = sm[0];
    __syncthreads();
    return v;
}

// per-row fused norms + act quant (256 threads)
template<int W, int WHICH>
__device__ __forceinline__ void actquant_row(const float* __restrict__ xrow,
                                             const float* __restrict__ nw,
                                             int row) {
    constexpr int VPT = W / 1024;
    const int tid = threadIdx.x;
    const float4* xr = (const float4*)xrow;
    const float4* nw4 = (const float4*)nw;
    float4 x[VPT];
    float ss = 0.f;
    #pragma unroll
    for (int i = 0; i < VPT; i++) {
        x[i] = xr[tid + i * 256];
        ss += x[i].x * x[i].x + x[i].y * x[i].y + x[i].z * x[i].z + x[i].w * x[i].w;
    }
    ss = blockReduce<false>(ss);
    float r = rsqrtf(ss / (float)W + 1e-6f);
    float4 h[VPT]; float sum = 0.f, sq = 0.f;
    #pragma unroll
    for (int i = 0; i < VPT; i++) {
        float4 w4 = nw4[tid + i * 256];
        h[i].x = w4.x * x[i].x * r; h[i].y = w4.y * x[i].y * r;
        h[i].z = w4.z * x[i].z * r; h[i].w = w4.w * x[i].w * r;
        sum += h[i].x + h[i].y + h[i].z + h[i].w;
        sq  += h[i].x * h[i].x + h[i].y * h[i].y + h[i].z * h[i].z + h[i].w * h[i].w;
    }
    sum = blockReduce<false>(sum);
    sq  = blockReduce<false>(sq);
    float mean = sum / (float)W;
    float var  = sq / (float)W - mean * mean;
    float rv = rsqrtf(var + 1e-5f);
    float amax = 0.f;
    #pragma unroll
    for (int i = 0; i < VPT; i++) {
        h[i].x = (h[i].x - mean) * rv; h[i].y = (h[i].y - mean) * rv;
        h[i].z = (h[i].z - mean) * rv; h[i].w = (h[i].w - mean) * rv;
        amax = fmaxf(amax, fmaxf(fmaxf(fabsf(h[i].x), fabsf(h[i].y)),
                                 fmaxf(fabsf(h[i].z), fabsf(h[i].w))));
    }
    amax = blockReduce<true>(amax);
    float scale = 127.f / fmaxf(amax, 1e-5f);
    bf16* Q = WHICH ? g_Yq : g_Aq;
    #pragma unroll
    for (int i = 0; i < VPT; i++) {
        bf16 o[4];
        float c[4] = {h[i].x, h[i].y, h[i].z, h[i].w};
        #pragma unroll
        for (int j = 0; j < 4; j++) {
            float q = rintf(c[j] * scale);
            o[j] = __float2bfloat16(fminf(fmaxf(q, -128.f), 127.f));
        }
        *(uint2*)(Q + (size_t)row * W + (tid + i * 256) * 4) = *(uint2*)o;
    }
    if (tid == 0) (WHICH ? g_sY : g_sA)[row] = scale;
}

// ---------------- persistent prep ----------------
#define NQ1 ((long)D_IN_PROJ_ * DIMX / 4)
#define NQ2 ((long)DIMX * D_INNER_ / 4)
#define NQP ((long)(NPAD_IN_ - D_IN_PROJ_) * DIMX / 4)
__global__ void __launch_bounds__(256) k_prep(const float* __restrict__ w1,
                                              const float* __restrict__ w2,
                                              const float* __restrict__ hidden,
                                              const float* __restrict__ norm_w) {
    const int cta = blockIdx.x, tid = threadIdx.x;

    for (int row = cta; row < MROWS_; row += PREP_CTAS)
        actquant_row<DIMX, 0>(hidden + (size_t)row * DIMX, norm_w, row);

    float s1 = 0.f, s2 = 0.f;
    for (long i = (long)cta * 256 + tid; i < NQ1; i += (long)PREP_CTAS * 256) {
        float4 v = ((const float4*)w1)[i];
        s1 += fabsf(v.x) + fabsf(v.y) + fabsf(v.z) + fabsf(v.w);
    }
    for (long i = (long)cta * 256 + tid; i < NQ2; i += (long)PREP_CTAS * 256) {
        float4 v = ((const float4*)w2)[i];
        s2 += fabsf(v.x) + fabsf(v.y) + fabsf(v.z) + fabsf(v.w);
    }
    s1 = blockReduce<false>(s1);
    s2 = blockReduce<false>(s2);
    if (tid == 0) { g_wpartA[cta] = s1; g_wpartB[cta] = s2; }

    __threadfence();
    __syncthreads();
    if (tid == 0) {
        unsigned long long old = atomicAdd(&g_prep_ctr, 1ull);
        unsigned long long target = (old / PREP_CTAS + 1ull) * PREP_CTAS;
        while (*((volatile unsigned long long*)&g_prep_ctr) < target) { }
    }
    __syncthreads();
    __threadfence();

    float a = 0.f, b = 0.f;
    for (int i = 0; i < PREP_CTAS; i++) { a += g_wpartA[i]; b += g_wpartB[i]; }
    const float sc0 = fmaxf(a / ((float)D_IN_PROJ_ * (float)DIMX), 1e-5f);
    const float sc1 = fmaxf(b / ((float)DIMX * (float)D_INNER_), 1e-5f);

    for (long q = (long)cta * 256 + tid; q < NQ1 + NQ2 + NQP; q += (long)PREP_CTAS * 256) {
        const float* w; bf16* dst; float sc; long i;
        if (q < NQ1) { w = w1; dst = g_WqIn;  sc = sc0; i = q * 4; }
        else if (q < NQ1 + NQ2) { w = w2; dst = g_WqOut; sc = sc1; i = (q - NQ1) * 4; }
        else {
            long i2 = (q - NQ1 - NQ2) * 4;
            *(uint2*)(g_WqIn + (size_t)D_IN_PROJ_ * DIMX + i2) = make_uint2(0, 0);
            continue;
        }
        float4 v = *(const float4*)(w + i);
        float vv[4] = {v.x, v.y, v.z, v.w};
        bf16 o[4];
        #pragma unroll
        for (int j = 0; j < 4; j++) {
            float ws = vv[j] / sc;
            float qq = (ws >= 0.f) ? floorf(ws + 0.5f) : ceilf(ws - 0.5f);
            o[j] = __float2bfloat16(fminf(fmaxf(qq, -1.f), 1.f));
        }
        *(uint2*)(dst + i) = *(uint2*)o;
    }
}

// ---------------- standalone actquant (Y -> Yq) ----------------
template<int W, int WHICH>
__global__ void k_actquant(const float* __restrict__ X, const float* __restrict__ nw) {
    const int row = blockIdx.x;
    actquant_row<W, WHICH>((WHICH ? g_Y : X) + (size_t)row * W, nw, row);
}

// ---------------- pipelined bf16 mma.sync GEMM: BK=64, 3 stages -----------
#define BMg 128
#define BNg 128
#define BKg 64
#define LDSg 72                         // 64 data + 8 pad (bf16 units)
#define STG_ELEMS (BMg * LDSg)          // 9216
#define STG_BYTES (2 * STG_ELEMS * 2)   // 36864
#define GEMM_SMEM (3 * STG_BYTES)       // 110592

template<int MODE>
__global__ void __launch_bounds__(256, 2) k_gemm(const float* __restrict__ resid,
                                                 float* __restrict__ outp) {
    constexpr int K = MODE ? D_INNER_ : DIMX;
    constexpr int N = MODE ? DIMX : D_IN_PROJ_;
    constexpr int NS = K / BKg;

    const bf16*  __restrict__ A  = MODE ? g_Yq : g_Aq;
    const bf16*  __restrict__ Bw = MODE ? g_WqOut : g_WqIn;
    const float* __restrict__ rs = MODE ? g_sY : g_sA;
    float*       __restrict__ C  = MODE ? outp : g_ZX;

    extern __shared__ char smem[];
    const uint32_t sb = smem_u32(smem);

    const int tid = threadIdx.x;
    const int lane = tid & 31, wid = tid >> 5;
    const int wm = wid & 1, wn = wid >> 1;
    const int m0 = blockIdx.y * BMg, n0 = blockIdx.x * BNg;
    const int mw = wm * 64, nwp = wn * 32;

    float acc[4][4][4];
    #pragma unroll
    for (int a = 0; a < 4; a++)
        #pragma unroll
        for (int b = 0; b < 4; b++)
            #pragma unroll
            for (int c = 0; c < 4; c++) acc[a][b][c] = 0.f;

    // copy plan: 2048 chunks of 16B per stage (A 1024 + B 1024); 8 per thread
    const bf16* gsrc[8];
    uint32_t sdst[8];
    #pragma unroll
    for (int i = 0; i < 8; i++) {
        int q = tid + i * 256;
        if (q < 1024) {
            int row = q >> 3, c = q & 7;
            gsrc[i] = A + (size_t)(m0 + row) * K + c * 8;
            sdst[i] = (uint32_t)(row * LDSg + c * 8) * 2;
        } else {
            int qq = q - 1024, row = qq >> 3, c = qq & 7;
            gsrc[i] = Bw + (size_t)(n0 + row) * K + c * 8;
            sdst[i] = (uint32_t)(STG_ELEMS + row * LDSg + c * 8) * 2;
        }
    }

    #define LOAD_STAGE(s_, slot_) do { \
        uint32_t base_ = sb + (uint32_t)(slot_) * STG_BYTES; \
        _Pragma("unroll") \
        for (int i_ = 0; i_ < 8; i_++) \
            asm volatile("cp.async.cg.shared.global [%0], [%1], 16;" \
                :: "r"(base_ + sdst[i_]), "l"(gsrc[i_] + (s_) * BKg) : "memory"); \
        asm volatile("cp.async.commit_group;" ::: "memory"); \
    } while (0)

    uint32_t aOff[4], bOff[2];
    {
        int rA = mw + (lane & 15);
        int cA = (lane >> 4) * 8;
        #pragma unroll
        for (int fm = 0; fm < 4; fm++)
            aOff[fm] = (uint32_t)((rA + fm * 16) * LDSg + cA) * 2;
        int rB = nwp + ((lane >> 4) << 3) + (lane & 7);
        int cB = ((lane >> 3) & 1) * 8;
        #pragma unroll
        for (int fb = 0; fb < 2; fb++)
            bOff[fb] = (uint32_t)(STG_ELEMS + (rB + fb * 16) * LDSg + cB) * 2;
    }

    LOAD_STAGE(0, 0); LOAD_STAGE(1, 1);

    int slot = 0, lslot = 2;
    for (int s = 0; s < NS; s++) {
        asm volatile("cp.async.wait_group 1;" ::: "memory");
        __syncthreads();
        if (s + 2 < NS) {
            LOAD_STAGE(s + 2, lslot);
            lslot = (lslot == 2) ? 0 : lslot + 1;
        }

        const uint32_t base = sb + (uint32_t)slot * STG_BYTES;
        slot = (slot == 2) ? 0 : slot + 1;
        #pragma unroll
        for (int ks = 0; ks < BKg; ks += 16) {
            unsigned af[4][4], bfr[4][2];
            #pragma unroll
            for (int fm = 0; fm < 4; fm++)
                asm volatile("ldmatrix.sync.aligned.m8n8.x4.shared.b16 {%0,%1,%2,%3}, [%4];"
                    : "=r"(af[fm][0]), "=r"(af[fm][1]), "=r"(af[fm][2]), "=r"(af[fm][3])
                    : "r"(base + aOff[fm] + (uint32_t)(ks * 2)));
            #pragma unroll
            for (int fb = 0; fb < 2; fb++) {
                unsigned q0, q1, q2, q3;
                asm volatile("ldmatrix.sync.aligned.m8n8.x4.shared.b16 {%0,%1,%2,%3}, [%4];"
                    : "=r"(q0), "=r"(q1), "=r"(q2), "=r"(q3)
                    : "r"(base + bOff[fb] + (uint32_t)(ks * 2)));
                bfr[fb * 2][0] = q0; bfr[fb * 2][1] = q1;
                bfr[fb * 2 + 1][0] = q2; bfr[fb * 2 + 1][1] = q3;
            }
            #pragma unroll
            for (int fm = 0; fm < 4; fm++)
                #pragma unroll
                for (int fn = 0; fn < 4; fn++)
                    asm volatile("mma.sync.aligned.m16n8k16.row.col.f32.bf16.bf16.f32 "
                        "{%0,%1,%2,%3},{%4,%5,%6,%7},{%8,%9},{%0,%1,%2,%3};"
                        : "+f"(acc[fm][fn][0]), "+f"(acc[fm][fn][1]),
                          "+f"(acc[fm][fn][2]), "+f"(acc[fm][fn][3])
                        : "r"(af[fm][0]), "r"(af[fm][1]), "r"(af[fm][2]), "r"(af[fm][3]),
                          "r"(bfr[fn][0]), "r"(bfr[fn][1]));
        }
    }

    const int mr = m0 + mw + (lane >> 2);
    const int nc = n0 + nwp + (lane & 3) * 2;
    #pragma unroll
    for (int fm = 0; fm < 4; fm++) {
        int m = mr + fm * 16;
        float inv0 = 1.f / rs[m];
        float inv1 = 1.f / rs[m + 8];
        #pragma unroll
        for (int fn = 0; fn < 4; fn++) {
            int n = nc + fn * 8;
            if (n < N) {
                size_t o0 = (size_t)m * N + n;
                size_t o8 = (size_t)(m + 8) * N + n;
                float v0 = acc[fm][fn][0] * inv0;
                float v1 = acc[fm][fn][1] * inv0;
                float v2 = acc[fm][fn][2] * inv1;
                float v3 = acc[fm][fn][3] * inv1;
                if (MODE) {
                    v0 += resid[o0]; v1 += resid[o0 + 1];
                    v2 += resid[o8]; v3 += resid[o8 + 1];
                }
                C[o0] = v0; C[o0 + 1] = v1; C[o8] = v2; C[o8 + 1] = v3;
            }
        }
    }
    #undef LOAD_STAGE
}

// ---------------- causal conv1d + silu ----------------
__global__ void k_conv(const float* __restrict__ cw, const float* __restrict__ cb) {
    int c = blockIdx.x * 256 + threadIdx.x;
    if (c >= CONV_DIM_) return;
    int b = blockIdx.y >> 5;
    int s0 = (blockIdx.y & 31) * 64;
    const float* src = g_ZX + (size_t)(b * SEQ_) * D_IN_PROJ_ + D_INNER_ + c;
    float*       dst = g_XC + (size_t)(b * SEQ_) * CONV_DIM_ + c;
    const float w0 = cw[c * 4], w1 = cw[c * 4 + 1], w2 = cw[c * 4 + 2], w3 = cw[c * 4 + 3];
    const float bias = cb[c];
    float xm3 = 0.f, xm2 = 0.f, xm1 = 0.f;
    if (s0 > 0) {
        xm3 = src[(size_t)(s0 - 3) * D_IN_PROJ_];
        xm2 = src[(size_t)(s0 - 2) * D_IN_PROJ_];
        xm1 = src[(size_t)(s0 - 1) * D_IN_PROJ_];
    }
    #pragma unroll 8
    for (int l = s0; l < s0 + 64; l++) {
        float x0 = src[(size_t)l * D_IN_PROJ_];
        float acc = fmaf(w3, x0, fmaf(w2, xm1, fmaf(w1, xm2, fmaf(w0, xm3, bias))));
        dst[(size_t)l * CONV_DIM_] = acc / (1.f + expf(-acc));
        xm3 = xm2; xm2 = xm1; xm1 = x0;
    }
}

// ---------------- PASS 1: per-chunk local scan ----------------
__global__ void __launch_bounds__(512) k_scan1(const float* __restrict__ A_log,
                                               const float* __restrict__ Dv,
                                               const float* __restrict__ dt_bias) {
    const int chunk = blockIdx.x, bh = blockIdx.y;
    const int h = bh & (NHEADS_ - 1);
    const int b = bh >> 6;
    const int l0 = chunk * LCH_;
    const int t = threadIdx.x;
    const int pc = t & 63, gc = t >> 6, n0 = gc * 16;

    __shared__ __align__(16) float xs[2][4][64];
    __shared__ __align__(16) float Bsh[2][4][128], Csh[2][4][128];
    __shared__ __align__(16) float ypart[2][4][8][64];
    __shared__ float sdt[2][4], sdA[2][4];

    const float Ah   = -expf(A_log[h]);
    const float Dh   = Dv[h];
    const float bias = dt_bias[h];

    u64 h2[8];
    #pragma unroll
    for (int i = 0; i < 8; i++) h2[i] = 0ull;

    const float* gptr = nullptr;
    if      (t < 64)  gptr = g_XC + (size_t)(b * SEQ_) * CONV_DIM_ + h * 64 + t;
    else if (t < 192) gptr = g_XC + (size_t)(b * SEQ_) * CONV_DIM_ + D_INNER_ + (t - 64);
    else if (t < 320) gptr = g_XC + (size_t)(b * SEQ_) * CONV_DIM_ + D_INNER_ + D_STATE_ + (t - 192);
    else if (t == 320) gptr = g_ZX + (size_t)(b * SEQ_) * D_IN_PROJ_ + DT_OFF_ + h;
    const size_t stride = (t < 320) ? (size_t)CONV_DIM_ : (size_t)D_IN_PROJ_;

    float r[4] = {0.f, 0.f, 0.f, 0.f};
    if (gptr) {
        #pragma unroll
        for (int s = 0; s < 4; s++) r[s] = gptr[(size_t)(l0 + s) * stride];
    }
    float* yrow = g_Y + (size_t)(b * SEQ_ + l0) * D_INNER_ + h * 64;
    float* arow = g_alpha + (size_t)bh * SEQ_ + l0;
    float aprod = 1.f;

    for (int blk = 0; blk < LCH_ / 4; blk++) {
        const int p = blk & 1, q = p ^ 1;
        if (t < 64) {
            #pragma unroll
            for (int s = 0; s < 4; s++) xs[p][s][t] = r[s];
        } else if (t < 192) {
            #pragma unroll
            for (int s = 0; s < 4; s++) Bsh[p][s][t - 64] = r[s];
        } else if (t < 320) {
            #pragma unroll
            for (int s = 0; s < 4; s++) Csh[p][s][t - 192] = r[s];
        } else if (t == 320) {
            #pragma unroll
            for (int s = 0; s < 4; s++) {
                float d = r[s] + bias;
                float sp = fmaxf(d, 0.f) + log1pf(expf(-fabsf(d)));
                float dA = expf(sp * Ah);
                sdt[p][s] = sp; sdA[p][s] = dA;
                aprod *= dA; arow[4 * blk + s] = aprod;
            }
        }
        __syncthreads();

        if (blk > 0 && t < 256) {
            const int s = t >> 6, tt = t & 63;
            float ysum = 0.f;
            #pragma unroll
            for (int g = 0; g < 8; g++) ysum += ypart[q][s][g][tt];
            yrow[(size_t)(4 * (blk - 1) + s) * D_INNER_ + tt] = ysum + Dh * xs[q][s][tt];
        }

        float rn[4] = {0.f, 0.f, 0.f, 0.f};
        if (gptr && blk + 1 < LCH_ / 4) {
            #pragma unroll
            for (int s = 0; s < 4; s++)
                rn[s] = gptr[(size_t)(l0 + 4 * blk + 4 + s) * stride];
        }

        #pragma unroll
        for (int s = 0; s < 4; s++) {
            const float dA = sdA[p][s];
            const float cf = sdt[p][s] * xs[p][s][pc];
            const u64 dA2 = pk2(dA, dA);
            const u64 cf2 = pk2(cf, cf);
            const ulonglong2* Bv = (const ulonglong2*)&Bsh[p][s][n0];
            const ulonglong2* Cv = (const ulonglong2*)&Csh[p][s][n0];
            u64 y2a = 0ull, y2b = 0ull;
            #pragma unroll
            for (int i = 0; i < 4; i++) {
                ulonglong2 B2 = Bv[i];
                ulonglong2 C2 = Cv[i];
                h2[2 * i]     = fma2(h2[2 * i],     dA2, mul2(cf2, B2.x));
                y2a = fma2(h2[2 * i],     C2.x, y2a);
                h2[2 * i + 1] = fma2(h2[2 * i + 1], dA2, mul2(cf2, B2.y));
                y2b = fma2(h2[2 * i + 1], C2.y, y2b);
            }
            float la, ha, lb, hb;
            upk2(la, ha, y2a); upk2(lb, hb, y2b);
            ypart[p][s][gc][pc] = (la + ha) + (lb + hb);
        }

        #pragma unroll
        for (int s = 0; s < 4; s++) r[s] = rn[s];
    }
    __syncthreads();
    if (t < 256) {
        const int q = (LCH_ / 4 - 1) & 1;
        const int s = t >> 6, tt = t & 63;
        float ysum = 0.f;
        #pragma unroll
        for (int g = 0; g < 8; g++) ysum += ypart[q][s][g][tt];
        yrow[(size_t)(LCH_ - 4 + s) * D_INNER_ + tt] = ysum + Dh * xs[q][s][tt];
    }
    float* srow = g_S + ((size_t)bh * NCHUNK_ + chunk) * 8192 + (size_t)pc * 128 + n0;
    float4* s4 = (float4*)srow;
    #pragma unroll
    for (int i = 0; i < 4; i++) {
        float4 v;
        upk2(v.x, v.y, h2[2 * i]);
        upk2(v.z, v.w, h2[2 * i + 1]);
        s4[i] = v;
    }
}

// ---------------- PASS 2: chunk-state prefix ----------------
__global__ void __launch_bounds__(512) k_scan2() {
    const int bh = blockIdx.x, t = threadIdx.x;
    float4 H[4];
    #pragma unroll
    for (int i = 0; i < 4; i++) H[i] = make_float4(0.f, 0.f, 0.f, 0.f);
    for (int c = 0; c < NCHUNK_; c++) {
        if (c > 0) {
            float4* hw = (float4*)(g_H + ((size_t)bh * NCHUNK_ + c) * 8192) + t * 4;
            #pragma unroll
            for (int i = 0; i < 4; i++) hw[i] = H[i];
        }
        float P = g_alpha[(size_t)bh * SEQ_ + c * LCH_ + LCH_ - 1];
        const float4* sv = (const float4*)(g_S + ((size_t)bh * NCHUNK_ + c) * 8192) + t * 4;
        #pragma unroll
        for (int i = 0; i < 4; i++) {
            float4 s = sv[i];
            H[i].x = fmaf(P, H[i].x, s.x);
            H[i].y = fmaf(P, H[i].y, s.y);
            H[i].z = fmaf(P, H[i].z, s.z);
            H[i].w = fmaf(P, H[i].w, s.w);
        }
    }
}

// ---------------- PASS 3: correction + gating ----------------
__global__ void __launch_bounds__(512, 2) k_scan3() {
    extern __shared__ float Cs[];
    __shared__ __align__(16) float ypart3[8][8][64];
    __shared__ float alf[LCH_];

    const int chunk = blockIdx.x, bh = blockIdx.y;
    const int h = bh & (NHEADS_ - 1);
    const int b = bh >> 6;
    const int l0 = chunk * LCH_;
    const int t = threadIdx.x;
    const int pc = t & 63, gc = t >> 6, n0 = gc * 16;

    {
        const float* cbase = g_XC + (size_t)(b * SEQ_ + l0) * CONV_DIM_
                           + D_INNER_ + D_STATE_;
        #pragma unroll
        for (int k = 0; k < 8; k++) {
            int idx = t + k * 512;
            int row = idx >> 5, c4 = idx & 31;
            ((float4*)Cs)[idx] =
                *(const float4*)(cbase + (size_t)row * CONV_DIM_ + c4 * 4);
        }
    }
    if (t < LCH_) alf[t] = g_alpha[(size_t)bh * SEQ_ + l0 + t];

    u64 H2[8];
    if (chunk > 0) {
        const float4* hv = (const float4*)(g_H + ((size_t)bh * NCHUNK_ + chunk) * 8192
                                           + (size_t)pc * 128 + n0);
        #pragma unroll
        for (int i = 0; i < 4; i++) {
            float4 v = hv[i];
            H2[2 * i]     = pk2(v.x, v.y);
            H2[2 * i + 1] = pk2(v.z, v.w);
        }
    } else {
        #pragma unroll
        for (int i = 0; i < 8; i++) H2[i] = 0ull;
    }
    __syncthreads();

    float* yrow = g_Y + (size_t)(b * SEQ_ + l0) * D_INNER_ + h * 64;
    const float* zrow = g_ZX + (size_t)(b * SEQ_ + l0) * D_IN_PROJ_ + h * 64;

    for (int lb = 0; lb < 16; lb++) {
        #pragma unroll
        for (int j = 0; j < 8; j++) {
            int l = lb * 8 + j;
            const ulonglong2* C2 = (const ulonglong2*)&Cs[l * 128 + n0];
            u64 y2 = 0ull;
            #pragma unroll
            for (int i = 0; i < 4; i++) {
                ulonglong2 c2 = C2[i];
                y2 = fma2(H2[2 * i], c2.x, y2);
                y2 = fma2(H2[2 * i + 1], c2.y, y2);
            }
            float lo, hi; upk2(lo, hi, y2);
            ypart3[j][gc][pc] = lo + hi;
        }
        __syncthreads();
        if (t < 256) {
            const int j0 = (t >> 6) * 2, tt = t & 63;
            #pragma unroll
            for (int jo = 0; jo < 2; jo++) {
                int j = j0 + jo;
                int l = lb * 8 + j;
                float corr = 0.f;
                #pragma unroll
                for (int g = 0; g < 8; g++) corr += ypart3[j][g][tt];
                float yl = yrow[(size_t)l * D_INNER_ + tt];
                float zz = zrow[(size_t)l * D_IN_PROJ_ + tt];
                float yo = (yl + alf[l] * corr) * (zz / (1.f + expf(-zz)));
                yrow[(size_t)l * D_INNER_ + tt] = yo;
            }
        }
        __syncthreads();
    }
}

// ---------------- launch ----------------
extern "C" void kernel_launch(void* const* d_in, const int* in_sizes, int n_in,
                              void* d_out, int out_size) {
    const float* hidden     = (const float*)d_in[0];
    const float* in_proj    = (const float*)d_in[1];
    const float* out_proj   = (const float*)d_in[2];
    const float* conv_w     = (const float*)d_in[3];
    const float* conv_b     = (const float*)d_in[4];
    const float* A_log      = (const float*)d_in[5];
    const float* Dv         = (const float*)d_in[6];
    const float* dt_bias    = (const float*)d_in[7];
    const float* norm_w     = (const float*)d_in[8];
    const float* out_norm_w = (const float*)d_in[9];
    float* out = (float*)d_out;

    cudaFuncSetAttribute(k_gemm<0>, cudaFuncAttributeMaxDynamicSharedMemorySize, GEMM_SMEM);
    cudaFuncSetAttribute(k_gemm<1>, cudaFuncAttributeMaxDynamicSharedMemorySize, GEMM_SMEM);
    cudaFuncSetAttribute(k_scan3, cudaFuncAttributeMaxDynamicSharedMemorySize, 65536);

    k_prep<<<PREP_CTAS, 256>>>(in_proj, out_proj, hidden, norm_w);                   // 1
    k_gemm<0><<<dim3((D_IN_PROJ_ + 127) / 128, MROWS_ / 128), 256, GEMM_SMEM>>>(nullptr, nullptr); // 2
    k_conv<<<dim3((CONV_DIM_ + 255) / 256, BATCH_ * 32), 256>>>(conv_w, conv_b);     // 3
    k_scan1<<<dim3(NCHUNK_, BATCH_ * NHEADS_), 512>>>(A_log, Dv, dt_bias);           // 4 <- captured
    k_scan2<<<BATCH_ * NHEADS_, 512>>>();                                            // 5
    k_scan3<<<dim3(NCHUNK_, BATCH_ * NHEADS_), 512, 65536>>>();                      // 6
    k_actquant<D_INNER_, 1><<<MROWS_, 256>>>(nullptr, out_norm_w);                   // 7
    k_gemm<1><<<dim3(DIMX / 128, MROWS_ / 128), 256, GEMM_SMEM>>>(hidden, out);      // 8
}